// round 1
// baseline (speedup 1.0000x reference)
#include <cuda_runtime.h>

// ---------------- problem constants ----------------
#define BATCH 32
#define TDIM  2048
#define KP    17
#define HID   64
#define NPOS  (TDIM * KP)      // 34816 positions per batch element
#define TTILE 16               // time steps per CTA

// ---------------- device scratch (no allocations allowed) ----------------
__device__ float g_bufA[(size_t)BATCH * TDIM * KP * HID];   // 285 MB
__device__ float g_bufB[(size_t)BATCH * TDIM * KP * HID];   // 285 MB
__device__ float g_M0[9 * 64];        // folded (Gw @ Wj^T) for block 0 (Cin=3)
__device__ float g_M1[192 * 64];      // block 1
__device__ float g_M2[192 * 64];      // block 2
__device__ float g_part[BATCH * 64 * 64];   // pool partials [b][slice][c]

// ---------------- weight folding: M_b[j*CIN+c][o] = sum_h gw[c][h] * tw[o][h][j] ----------------
__global__ void prep_kernel(const float* __restrict__ gw0,
                            const float* __restrict__ gw1,
                            const float* __restrict__ gw2,
                            const float* __restrict__ tcw) {
    int id = blockIdx.x * blockDim.x + threadIdx.x;
    const int n0 = 9 * 64, n1 = 192 * 64, n2 = 192 * 64;
    if (id >= n0 + n1 + n2) return;

    int blk, cin, e;
    const float* gw;
    float* M;
    if (id < n0)            { blk = 0; cin = 3;  gw = gw0; M = g_M0; e = id; }
    else if (id < n0 + n1)  { blk = 1; cin = 64; gw = gw1; M = g_M1; e = id - n0; }
    else                    { blk = 2; cin = 64; gw = gw2; M = g_M2; e = id - n0 - n1; }

    int km = e / 64, o = e % 64;
    int j = km / cin, c = km % cin;
    const float* tw = tcw + (size_t)blk * HID * HID * 3;   // tw[o][h][j]
    float s = 0.f;
    for (int h = 0; h < HID; ++h)
        s = fmaf(gw[c * HID + h], tw[(o * HID + h) * 3 + j], s);
    M[km * 64 + o] = s;
}

// ---------------- fused STGCN block ----------------
// pre[t,k,o] = sum_j sum_c x[t+(j-1)*DIL, k, c] * M[j*CIN+c][o]   (zero-padded in t)
// out[t,v,o] = relu( (sum_k adj[k,v]*pre[t,k,o]) * bnInv[o] + bnBeta[o] ) (+ x[t,v,o] if RES)
template <int CIN, int DIL, bool RES>
__global__ void __launch_bounds__(256) stgn_block_kernel(
    const float* __restrict__ xin,
    const float* __restrict__ Mg,
    const float* __restrict__ adj,
    const float* __restrict__ bns, const float* __restrict__ bnb,
    const float* __restrict__ bnm, const float* __restrict__ bnv,
    float* __restrict__ out)
{
    constexpr int KW = 3 * CIN;                       // folded reduction width
    constexpr int HR = TTILE + 2 * DIL;               // halo time rows
    constexpr int PR = HR * KP;                       // halo positions
    constexpr int XS = (CIN % 4 == 0) ? CIN + 4 : CIN + 1;  // padded X row stride
    constexpr int OP = TTILE * KP;                    // 272 output positions
    constexpr int NQ = OP / 4;                        // 68 row quads

    extern __shared__ float sm[];
    float* sM   = sm;                  // KW*64
    float* sX   = sM + KW * 64;        // PR*XS
    float* sP   = sX + PR * XS;        // OP*64
    float* sAdj = sP + OP * 64;        // 289

    const int tid = threadIdx.x;
    const int b   = blockIdx.y;
    const int t0  = blockIdx.x * TTILE;

    // --- load weights / adj / halo'd input tile ---
    for (int i = tid; i < KW * 64; i += 256) sM[i] = Mg[i];
    for (int i = tid; i < KP * KP; i += 256) sAdj[i] = adj[i];
    {
        const int base_t = t0 - DIL;
        for (int i = tid; i < PR * CIN; i += 256) {
            int pr = i / CIN;          // = h*KP + kk
            int c  = i % CIN;
            int h  = pr / KP;
            int kk = pr % KP;
            int t  = base_t + h;
            float v = 0.f;
            if (t >= 0 && t < TDIM)
                v = xin[((b * TDIM + t) * KP + kk) * CIN + c];
            sX[pr * XS + c] = v;
        }
    }
    __syncthreads();

    // --- GEMM: each thread computes 4 rows x 8 cols per iteration ---
    const int cg = tid & 7;    // column group (8 cols each)
    const int rt = tid >> 3;   // row-quad thread 0..31

    for (int iter = 0; iter < 3; ++iter) {
        int q = rt + 32 * iter;
        if (q >= NQ) break;

        int rowoff[4][3];
#pragma unroll
        for (int i = 0; i < 4; ++i) {
            int p  = 4 * q + i;
            int tt = p / KP, kk = p % KP;
#pragma unroll
            for (int j = 0; j < 3; ++j)
                rowoff[i][j] = ((tt + j * DIL) * KP + kk) * XS;
        }

        float acc[4][8];
#pragma unroll
        for (int i = 0; i < 4; ++i)
#pragma unroll
            for (int n = 0; n < 8; ++n) acc[i][n] = 0.f;

#pragma unroll
        for (int j = 0; j < 3; ++j) {
            if constexpr (CIN % 4 == 0) {
#pragma unroll 2
                for (int c = 0; c < CIN; c += 4) {
                    float4 a0 = *(const float4*)(sX + rowoff[0][j] + c);
                    float4 a1 = *(const float4*)(sX + rowoff[1][j] + c);
                    float4 a2 = *(const float4*)(sX + rowoff[2][j] + c);
                    float4 a3 = *(const float4*)(sX + rowoff[3][j] + c);
                    const float* ap0 = (const float*)&a0;
                    const float* ap1 = (const float*)&a1;
                    const float* ap2 = (const float*)&a2;
                    const float* ap3 = (const float*)&a3;
#pragma unroll
                    for (int u = 0; u < 4; ++u) {
                        const float* mp = sM + (j * CIN + c + u) * 64 + (cg << 3);
                        float4 m0 = *(const float4*)mp;
                        float4 m1 = *(const float4*)(mp + 4);
                        float av[4] = {ap0[u], ap1[u], ap2[u], ap3[u]};
                        const float* mv = (const float*)&m0;
                        const float* mw = (const float*)&m1;
#pragma unroll
                        for (int i = 0; i < 4; ++i) {
#pragma unroll
                            for (int n = 0; n < 4; ++n) {
                                acc[i][n]     = fmaf(av[i], mv[n], acc[i][n]);
                                acc[i][n + 4] = fmaf(av[i], mw[n], acc[i][n + 4]);
                            }
                        }
                    }
                }
            } else {
                for (int c = 0; c < CIN; ++c) {
                    float av[4];
#pragma unroll
                    for (int i = 0; i < 4; ++i) av[i] = sX[rowoff[i][j] + c];
                    const float* mp = sM + (j * CIN + c) * 64 + (cg << 3);
                    float4 m0 = *(const float4*)mp;
                    float4 m1 = *(const float4*)(mp + 4);
                    const float* mv = (const float*)&m0;
                    const float* mw = (const float*)&m1;
#pragma unroll
                    for (int i = 0; i < 4; ++i) {
#pragma unroll
                        for (int n = 0; n < 4; ++n) {
                            acc[i][n]     = fmaf(av[i], mv[n], acc[i][n]);
                            acc[i][n + 4] = fmaf(av[i], mw[n], acc[i][n + 4]);
                        }
                    }
                }
            }
        }

        // stage pre-graph-mix results to smem
#pragma unroll
        for (int i = 0; i < 4; ++i) {
            float* pp = sP + (4 * q + i) * 64 + (cg << 3);
            *(float4*)pp       = make_float4(acc[i][0], acc[i][1], acc[i][2], acc[i][3]);
            *(float4*)(pp + 4) = make_float4(acc[i][4], acc[i][5], acc[i][6], acc[i][7]);
        }
    }
    __syncthreads();

    // --- epilogue: graph mix over k, BN, ReLU, residual ---
    const int o  = tid & 63;
    const int pg = tid >> 6;   // 0..3
    const float bsv = __ldg(bns + o);
    const float inv = bsv * rsqrtf(__ldg(bnv + o) + 1e-5f);
    const float bet = __ldg(bnb + o) - __ldg(bnm + o) * inv;

    for (int p = pg; p < OP; p += 4) {
        int tt = p / KP, v = p % KP;
        float s = 0.f;
#pragma unroll
        for (int k = 0; k < KP; ++k)
            s = fmaf(sAdj[k * KP + v], sP[(tt * KP + k) * 64 + o], s);
        float val = fmaf(s, inv, bet);
        val = fmaxf(val, 0.f);
        int gpos = (b * TDIM + t0 + tt) * KP + v;
        if (RES) val += xin[gpos * CIN + o];
        out[gpos * HID + o] = val;
    }
}

// ---------------- mean pool (stage 1): deterministic slice partials ----------------
__global__ void pool_kernel(const float* __restrict__ x) {
    __shared__ float red[4][64];
    const int b = blockIdx.y, sl = blockIdx.x;
    const int c = threadIdx.x & 63, g = threadIdx.x >> 6;
    const int CH = NPOS / 64;   // 544 positions per slice
    const float* base = x + ((size_t)b * NPOS + sl * CH) * HID;
    float acc = 0.f;
    for (int p = g; p < CH; p += 4)
        acc += base[p * HID + c];
    red[g][c] = acc;
    __syncthreads();
    if (threadIdx.x < 64)
        g_part[(b * 64 + sl) * 64 + c] = red[0][c] + red[1][c] + red[2][c] + red[3][c];
}

// ---------------- pool stage 2 + LayerNorm + FC head ----------------
__global__ void head_kernel(const float* __restrict__ lns, const float* __restrict__ lnb,
                            const float* __restrict__ fw,  const float* __restrict__ fb,
                            float* __restrict__ outp) {
    __shared__ float f[64];
    __shared__ float mu_s, rv_s;
    const int b = blockIdx.x, tid = threadIdx.x;   // 64 threads

    float s = 0.f;
    for (int sl = 0; sl < 64; ++sl)
        s += g_part[(b * 64 + sl) * 64 + tid];
    float v = s * (1.0f / (float)NPOS);
    f[tid] = v;
    __syncthreads();
    if (tid == 0) {
        float m = 0.f;
        for (int i = 0; i < 64; ++i) m += f[i];
        m *= (1.0f / 64.0f);
        float va = 0.f;
        for (int i = 0; i < 64; ++i) { float d = f[i] - m; va = fmaf(d, d, va); }
        va *= (1.0f / 64.0f);
        mu_s = m;
        rv_s = rsqrtf(va + 1e-5f);
    }
    __syncthreads();
    float nf = (v - mu_s) * rv_s * lns[tid] + lnb[tid];
    __syncthreads();
    f[tid] = nf;
    __syncthreads();
    if (tid < 10) {
        float o = fb[tid];
        for (int c = 0; c < 64; ++c)
            o = fmaf(f[c], fw[c * 10 + tid], o);
        outp[b * 10 + tid] = o;
    }
}

// ---------------- launch ----------------
extern "C" void kernel_launch(void* const* d_in, const int* in_sizes, int n_in,
                              void* d_out, int out_size) {
    const float* kpts = (const float*)d_in[0];
    const float* adj  = (const float*)d_in[1];
    const float* gw0  = (const float*)d_in[2];
    const float* gw1  = (const float*)d_in[3];
    const float* gw2  = (const float*)d_in[4];
    const float* tcw  = (const float*)d_in[5];
    const float* bns  = (const float*)d_in[6];
    const float* bnb  = (const float*)d_in[7];
    const float* bnm  = (const float*)d_in[8];
    const float* bnv  = (const float*)d_in[9];
    const float* lns  = (const float*)d_in[10];
    const float* lnb  = (const float*)d_in[11];
    const float* fw   = (const float*)d_in[12];
    const float* fb   = (const float*)d_in[13];
    float* outp = (float*)d_out;

    float *bufA, *bufB, *M0, *M1, *M2;
    cudaGetSymbolAddress((void**)&bufA, g_bufA);
    cudaGetSymbolAddress((void**)&bufB, g_bufB);
    cudaGetSymbolAddress((void**)&M0, g_M0);
    cudaGetSymbolAddress((void**)&M1, g_M1);
    cudaGetSymbolAddress((void**)&M2, g_M2);

    // dynamic smem sizes (floats): M + X(padded) + P + adj
    const size_t smem0 = (size_t)(9 * 64   + 306 * 4  + 272 * 64 + 289) * 4;  //  78.0 KB
    const size_t smem1 = (size_t)(192 * 64 + 306 * 68 + 272 * 64 + 289) * 4;  // 203.2 KB
    const size_t smem2 = (size_t)(192 * 64 + 340 * 68 + 272 * 64 + 289) * 4;  // 212.4 KB
    cudaFuncSetAttribute(stgn_block_kernel<3, 1, false>,
                         cudaFuncAttributeMaxDynamicSharedMemorySize, (int)smem0);
    cudaFuncSetAttribute(stgn_block_kernel<64, 1, true>,
                         cudaFuncAttributeMaxDynamicSharedMemorySize, (int)smem1);
    cudaFuncSetAttribute(stgn_block_kernel<64, 2, true>,
                         cudaFuncAttributeMaxDynamicSharedMemorySize, (int)smem2);

    prep_kernel<<<(25152 + 255) / 256, 256>>>(gw0, gw1, gw2, tcw);

    dim3 grid(TDIM / TTILE, BATCH);   // 128 x 32
    stgn_block_kernel<3, 1, false><<<grid, 256, smem0>>>(
        kpts, M0, adj, bns + 0,  bnb + 0,  bnm + 0,  bnv + 0,  bufA);
    stgn_block_kernel<64, 1, true><<<grid, 256, smem1>>>(
        bufA, M1, adj, bns + 64, bnb + 64, bnm + 64, bnv + 64, bufB);
    stgn_block_kernel<64, 2, true><<<grid, 256, smem2>>>(
        bufB, M2, adj, bns + 128, bnb + 128, bnm + 128, bnv + 128, bufA);

    pool_kernel<<<dim3(64, BATCH), 256>>>(bufA);
    head_kernel<<<BATCH, 64>>>(lns, lnb, fw, fb, outp);
}

// round 2
// speedup vs baseline: 1.1435x; 1.1435x over previous
#include <cuda_runtime.h>

// ---------------- problem constants ----------------
#define BATCH 32
#define TDIM  2048
#define KP    17
#define HID   64
#define NPOS  (TDIM * KP)      // 34816 positions per batch element
#define TTILE 16               // time steps per CTA

// ---------------- device scratch (no allocations allowed) ----------------
__device__ float g_bufA[(size_t)BATCH * TDIM * KP * HID];   // 285 MB
__device__ float g_bufB[(size_t)BATCH * TDIM * KP * HID];   // 285 MB
__device__ float g_M0[9 * 64];        // folded (Gw @ Wj^T) for block 0 (Cin=3)
__device__ float g_M1[192 * 64];      // block 1
__device__ float g_M2[192 * 64];      // block 2
__device__ float g_part[BATCH * 64 * 64];   // pool partials [b][slice][c]

// ---------------- f32x2 helpers (double-pumped fp32 pipe on sm_103a) ----------------
__device__ __forceinline__ unsigned long long pack2_dup(float x) {
    unsigned long long r;
    unsigned int xb = __float_as_uint(x);
    asm("mov.b64 %0, {%1, %1};" : "=l"(r) : "r"(xb));
    return r;
}
__device__ __forceinline__ void fma2(unsigned long long& c, unsigned long long a,
                                     unsigned long long b) {
    asm("fma.rn.f32x2 %0, %1, %2, %3;" : "=l"(c) : "l"(a), "l"(b), "l"(c));
}
__device__ __forceinline__ float2 unpack2(unsigned long long v) {
    unsigned int lo, hi;
    asm("mov.b64 {%0, %1}, %2;" : "=r"(lo), "=r"(hi) : "l"(v));
    return make_float2(__uint_as_float(lo), __uint_as_float(hi));
}

// ---------------- weight folding: M_b[j*CIN+c][o] = sum_h gw[c][h] * tw[o][h][j] ----------------
__global__ void prep_kernel(const float* __restrict__ gw0,
                            const float* __restrict__ gw1,
                            const float* __restrict__ gw2,
                            const float* __restrict__ tcw) {
    int id = blockIdx.x * blockDim.x + threadIdx.x;
    const int n0 = 9 * 64, n1 = 192 * 64, n2 = 192 * 64;
    if (id >= n0 + n1 + n2) return;

    int blk, cin, e;
    const float* gw;
    float* M;
    if (id < n0)            { blk = 0; cin = 3;  gw = gw0; M = g_M0; e = id; }
    else if (id < n0 + n1)  { blk = 1; cin = 64; gw = gw1; M = g_M1; e = id - n0; }
    else                    { blk = 2; cin = 64; gw = gw2; M = g_M2; e = id - n0 - n1; }

    int km = e / 64, o = e % 64;
    int j = km / cin, c = km % cin;
    const float* tw = tcw + (size_t)blk * HID * HID * 3;   // tw[o][h][j]
    float s = 0.f;
    for (int h = 0; h < HID; ++h)
        s = fmaf(gw[c * HID + h], tw[(o * HID + h) * 3 + j], s);
    M[km * 64 + o] = s;
}

// ---------------- fused STGCN block ----------------
// pre[t,k,o] = sum_j sum_c x[t+(j-1)*DIL, k, c] * M[j*CIN+c][o]   (zero-padded in t)
// out[t,v,o] = relu( (sum_k adj[k,v]*pre[t,k,o]) * bnInv[o] + bnBeta[o] ) (+ x[t,v,o] if RES)
template <int CIN, int DIL, bool RES>
__global__ void __launch_bounds__(512) stgn_block_kernel(
    const float* __restrict__ xin,
    const float* __restrict__ Mg,
    const float* __restrict__ adj,
    const float* __restrict__ bns, const float* __restrict__ bnb,
    const float* __restrict__ bnm, const float* __restrict__ bnv,
    float* __restrict__ out)
{
    constexpr int KW = 3 * CIN;                       // folded reduction width
    constexpr int HR = TTILE + 2 * DIL;               // halo time rows
    constexpr int PR = HR * KP;                       // halo positions
    constexpr int XS = (CIN % 4 == 0) ? CIN + 4 : CIN + 1;  // padded X row stride
    constexpr int OP = TTILE * KP;                    // 272 output positions
    constexpr int NQ = OP / 4;                        // 68 row quads

    extern __shared__ float sm[];
    float* sM   = sm;                  // KW*64
    float* sX   = sM + KW * 64;        // PR*XS
    float* sP   = sX + PR * XS;        // OP*64
    float* sAdj = sP + OP * 64;        // 289

    const int tid = threadIdx.x;
    const int b   = blockIdx.y;
    const int t0  = blockIdx.x * TTILE;

    // --- load weights / adj / halo'd input tile ---
    for (int i = tid; i < KW * 64; i += 512) sM[i] = Mg[i];
    for (int i = tid; i < KP * KP; i += 512) sAdj[i] = adj[i];
    {
        const int base_t = t0 - DIL;
        for (int i = tid; i < PR * CIN; i += 512) {
            int pr = i / CIN;          // = h*KP + kk
            int c  = i % CIN;
            int h  = pr / KP;
            int kk = pr % KP;
            int t  = base_t + h;
            float v = 0.f;
            if (t >= 0 && t < TDIM)
                v = xin[((b * TDIM + t) * KP + kk) * CIN + c];
            sX[pr * XS + c] = v;
        }
    }
    __syncthreads();

    // --- GEMM: each thread computes 4 rows x 8 cols per iteration ---
    const int cg = tid & 7;    // column group (8 cols each)
    const int rt = tid >> 3;   // row-quad thread 0..63

    for (int iter = 0; iter < 2; ++iter) {
        int q = rt + 64 * iter;
        if (q >= NQ) break;

        int rowoff[4][3];
#pragma unroll
        for (int i = 0; i < 4; ++i) {
            int p  = 4 * q + i;
            int tt = p / KP, kk = p % KP;
#pragma unroll
            for (int j = 0; j < 3; ++j)
                rowoff[i][j] = ((tt + j * DIL) * KP + kk) * XS;
        }

        if constexpr (CIN % 4 == 0) {
            // f32x2 packed accumulators: 4 rows x 4 column-pairs (8 cols)
            unsigned long long acc2[4][4];
#pragma unroll
            for (int i = 0; i < 4; ++i)
#pragma unroll
                for (int n = 0; n < 4; ++n) acc2[i][n] = 0ULL;

#pragma unroll
            for (int j = 0; j < 3; ++j) {
#pragma unroll 2
                for (int c = 0; c < CIN; c += 4) {
                    float4 a0 = *(const float4*)(sX + rowoff[0][j] + c);
                    float4 a1 = *(const float4*)(sX + rowoff[1][j] + c);
                    float4 a2 = *(const float4*)(sX + rowoff[2][j] + c);
                    float4 a3 = *(const float4*)(sX + rowoff[3][j] + c);
                    const float* ap[4] = {(const float*)&a0, (const float*)&a1,
                                          (const float*)&a2, (const float*)&a3};
#pragma unroll
                    for (int u = 0; u < 4; ++u) {
                        const ulonglong2* mp = (const ulonglong2*)
                            (sM + (j * CIN + c + u) * 64 + (cg << 3));
                        ulonglong2 mA = mp[0];   // cols n..n+3   (2 pairs)
                        ulonglong2 mB = mp[1];   // cols n+4..n+7 (2 pairs)
#pragma unroll
                        for (int i = 0; i < 4; ++i) {
                            unsigned long long ad = pack2_dup(ap[i][u]);
                            fma2(acc2[i][0], ad, mA.x);
                            fma2(acc2[i][1], ad, mA.y);
                            fma2(acc2[i][2], ad, mB.x);
                            fma2(acc2[i][3], ad, mB.y);
                        }
                    }
                }
            }

            // stage pre-graph-mix results to smem
#pragma unroll
            for (int i = 0; i < 4; ++i) {
                float2 p0 = unpack2(acc2[i][0]);
                float2 p1 = unpack2(acc2[i][1]);
                float2 p2 = unpack2(acc2[i][2]);
                float2 p3 = unpack2(acc2[i][3]);
                float* pp = sP + (4 * q + i) * 64 + (cg << 3);
                *(float4*)pp       = make_float4(p0.x, p0.y, p1.x, p1.y);
                *(float4*)(pp + 4) = make_float4(p2.x, p2.y, p3.x, p3.y);
            }
        } else {
            float acc[4][8];
#pragma unroll
            for (int i = 0; i < 4; ++i)
#pragma unroll
                for (int n = 0; n < 8; ++n) acc[i][n] = 0.f;

#pragma unroll
            for (int j = 0; j < 3; ++j) {
                for (int c = 0; c < CIN; ++c) {
                    float av[4];
#pragma unroll
                    for (int i = 0; i < 4; ++i) av[i] = sX[rowoff[i][j] + c];
                    const float* mp = sM + (j * CIN + c) * 64 + (cg << 3);
                    float4 m0 = *(const float4*)mp;
                    float4 m1 = *(const float4*)(mp + 4);
                    const float* mv = (const float*)&m0;
                    const float* mw = (const float*)&m1;
#pragma unroll
                    for (int i = 0; i < 4; ++i) {
#pragma unroll
                        for (int n = 0; n < 4; ++n) {
                            acc[i][n]     = fmaf(av[i], mv[n], acc[i][n]);
                            acc[i][n + 4] = fmaf(av[i], mw[n], acc[i][n + 4]);
                        }
                    }
                }
            }
#pragma unroll
            for (int i = 0; i < 4; ++i) {
                float* pp = sP + (4 * q + i) * 64 + (cg << 3);
                *(float4*)pp       = make_float4(acc[i][0], acc[i][1], acc[i][2], acc[i][3]);
                *(float4*)(pp + 4) = make_float4(acc[i][4], acc[i][5], acc[i][6], acc[i][7]);
            }
        }
    }
    __syncthreads();

    // --- epilogue: graph mix over k, BN, ReLU, residual ---
    const int o  = tid & 63;
    const int pg = tid >> 6;   // 0..7
    const float bsv = __ldg(bns + o);
    const float inv = bsv * rsqrtf(__ldg(bnv + o) + 1e-5f);
    const float bet = __ldg(bnb + o) - __ldg(bnm + o) * inv;

    for (int p = pg; p < OP; p += 8) {
        int tt = p / KP, v = p % KP;
        float s = 0.f;
#pragma unroll
        for (int k = 0; k < KP; ++k)
            s = fmaf(sAdj[k * KP + v], sP[(tt * KP + k) * 64 + o], s);
        float val = fmaf(s, inv, bet);
        val = fmaxf(val, 0.f);
        int gpos = (b * TDIM + t0 + tt) * KP + v;
        if (RES) val += xin[gpos * CIN + o];
        out[gpos * HID + o] = val;
    }
}

// ---------------- mean pool (stage 1): deterministic slice partials ----------------
__global__ void pool_kernel(const float* __restrict__ x) {
    __shared__ float red[4][64];
    const int b = blockIdx.y, sl = blockIdx.x;
    const int c = threadIdx.x & 63, g = threadIdx.x >> 6;
    const int CH = NPOS / 64;   // 544 positions per slice
    const float* base = x + ((size_t)b * NPOS + sl * CH) * HID;
    float acc = 0.f;
    for (int p = g; p < CH; p += 4)
        acc += base[p * HID + c];
    red[g][c] = acc;
    __syncthreads();
    if (threadIdx.x < 64)
        g_part[(b * 64 + sl) * 64 + c] = red[0][c] + red[1][c] + red[2][c] + red[3][c];
}

// ---------------- pool stage 2 + LayerNorm + FC head ----------------
__global__ void head_kernel(const float* __restrict__ lns, const float* __restrict__ lnb,
                            const float* __restrict__ fw,  const float* __restrict__ fb,
                            float* __restrict__ outp) {
    __shared__ float f[64];
    __shared__ float mu_s, rv_s;
    const int b = blockIdx.x, tid = threadIdx.x;   // 64 threads

    float s = 0.f;
    for (int sl = 0; sl < 64; ++sl)
        s += g_part[(b * 64 + sl) * 64 + tid];
    float v = s * (1.0f / (float)NPOS);
    f[tid] = v;
    __syncthreads();
    if (tid == 0) {
        float m = 0.f;
        for (int i = 0; i < 64; ++i) m += f[i];
        m *= (1.0f / 64.0f);
        float va = 0.f;
        for (int i = 0; i < 64; ++i) { float d = f[i] - m; va = fmaf(d, d, va); }
        va *= (1.0f / 64.0f);
        mu_s = m;
        rv_s = rsqrtf(va + 1e-5f);
    }
    __syncthreads();
    float nf = (v - mu_s) * rv_s * lns[tid] + lnb[tid];
    __syncthreads();
    f[tid] = nf;
    __syncthreads();
    if (tid < 10) {
        float o = fb[tid];
        for (int c = 0; c < 64; ++c)
            o = fmaf(f[c], fw[c * 10 + tid], o);
        outp[b * 10 + tid] = o;
    }
}

// ---------------- launch ----------------
extern "C" void kernel_launch(void* const* d_in, const int* in_sizes, int n_in,
                              void* d_out, int out_size) {
    const float* kpts = (const float*)d_in[0];
    const float* adj  = (const float*)d_in[1];
    const float* gw0  = (const float*)d_in[2];
    const float* gw1  = (const float*)d_in[3];
    const float* gw2  = (const float*)d_in[4];
    const float* tcw  = (const float*)d_in[5];
    const float* bns  = (const float*)d_in[6];
    const float* bnb  = (const float*)d_in[7];
    const float* bnm  = (const float*)d_in[8];
    const float* bnv  = (const float*)d_in[9];
    const float* lns  = (const float*)d_in[10];
    const float* lnb  = (const float*)d_in[11];
    const float* fw   = (const float*)d_in[12];
    const float* fb   = (const float*)d_in[13];
    float* outp = (float*)d_out;

    float *bufA, *bufB, *M0, *M1, *M2;
    cudaGetSymbolAddress((void**)&bufA, g_bufA);
    cudaGetSymbolAddress((void**)&bufB, g_bufB);
    cudaGetSymbolAddress((void**)&M0, g_M0);
    cudaGetSymbolAddress((void**)&M1, g_M1);
    cudaGetSymbolAddress((void**)&M2, g_M2);

    // dynamic smem sizes (floats): M + X(padded) + P + adj
    const size_t smem0 = (size_t)(9 * 64   + 306 * 4  + 272 * 64 + 289) * 4;  //  78.0 KB
    const size_t smem1 = (size_t)(192 * 64 + 306 * 68 + 272 * 64 + 289) * 4;  // 203.2 KB
    const size_t smem2 = (size_t)(192 * 64 + 340 * 68 + 272 * 64 + 289) * 4;  // 212.4 KB
    cudaFuncSetAttribute(stgn_block_kernel<3, 1, false>,
                         cudaFuncAttributeMaxDynamicSharedMemorySize, (int)smem0);
    cudaFuncSetAttribute(stgn_block_kernel<64, 1, true>,
                         cudaFuncAttributeMaxDynamicSharedMemorySize, (int)smem1);
    cudaFuncSetAttribute(stgn_block_kernel<64, 2, true>,
                         cudaFuncAttributeMaxDynamicSharedMemorySize, (int)smem2);

    prep_kernel<<<(25152 + 255) / 256, 256>>>(gw0, gw1, gw2, tcw);

    dim3 grid(TDIM / TTILE, BATCH);   // 128 x 32
    stgn_block_kernel<3, 1, false><<<grid, 512, smem0>>>(
        kpts, M0, adj, bns + 0,  bnb + 0,  bnm + 0,  bnv + 0,  bufA);
    stgn_block_kernel<64, 1, true><<<grid, 512, smem1>>>(
        bufA, M1, adj, bns + 64, bnb + 64, bnm + 64, bnv + 64, bufB);
    stgn_block_kernel<64, 2, true><<<grid, 512, smem2>>>(
        bufB, M2, adj, bns + 128, bnb + 128, bnm + 128, bnv + 128, bufA);

    pool_kernel<<<dim3(64, BATCH), 256>>>(bufA);
    head_kernel<<<BATCH, 64>>>(lns, lnb, fw, fb, outp);
}

// round 3
// speedup vs baseline: 1.3288x; 1.1621x over previous
#include <cuda_runtime.h>

// ---------------- problem constants ----------------
#define BATCH 32
#define TDIM  2048
#define KP    17
#define HID   64
#define NPOS  (TDIM * KP)      // 34816 positions per batch element
#define TTILE 16               // time steps per CTA
#define NZMAX 5                // padded nonzeros per adjacency column (COCO max = 4)

// ---------------- device scratch (no allocations allowed) ----------------
__device__ float g_bufA[(size_t)BATCH * TDIM * KP * HID];   // 285 MB
__device__ float g_bufB[(size_t)BATCH * TDIM * KP * HID];   // 285 MB
__device__ float g_M0[9 * 64];        // folded (Gw @ Wj^T) for block 0 (Cin=3)
__device__ float g_M1[192 * 64];      // block 1
__device__ float g_M2[192 * 64];      // block 2
__device__ float2 g_adjT[KP * NZMAX]; // sparse adj: per v, {weight, bitcast(k*64)}
__device__ float g_part[BATCH * 64 * 64];   // pool partials [b][slice][c]

// ---------------- f32x2 helpers (double-pumped fp32 pipe on sm_103a) ----------------
__device__ __forceinline__ unsigned long long pack2_dup(float x) {
    unsigned long long r;
    unsigned int xb = __float_as_uint(x);
    asm("mov.b64 %0, {%1, %1};" : "=l"(r) : "r"(xb));
    return r;
}
__device__ __forceinline__ void fma2(unsigned long long& c, unsigned long long a,
                                     unsigned long long b) {
    asm("fma.rn.f32x2 %0, %1, %2, %3;" : "=l"(c) : "l"(a), "l"(b), "l"(c));
}
__device__ __forceinline__ float2 unpack2(unsigned long long v) {
    unsigned int lo, hi;
    asm("mov.b64 {%0, %1}, %2;" : "=r"(lo), "=r"(hi) : "l"(v));
    return make_float2(__uint_as_float(lo), __uint_as_float(hi));
}

// ---------------- weight folding: M_b[j*CIN+c][o] = sum_h gw[c][h] * tw[o][h][j] ----------------
__global__ void prep_kernel(const float* __restrict__ gw0,
                            const float* __restrict__ gw1,
                            const float* __restrict__ gw2,
                            const float* __restrict__ tcw) {
    int id = blockIdx.x * blockDim.x + threadIdx.x;
    const int n0 = 9 * 64, n1 = 192 * 64, n2 = 192 * 64;
    if (id >= n0 + n1 + n2) return;

    int blk, cin, e;
    const float* gw;
    float* M;
    if (id < n0)            { blk = 0; cin = 3;  gw = gw0; M = g_M0; e = id; }
    else if (id < n0 + n1)  { blk = 1; cin = 64; gw = gw1; M = g_M1; e = id - n0; }
    else                    { blk = 2; cin = 64; gw = gw2; M = g_M2; e = id - n0 - n1; }

    int km = e / 64, o = e % 64;
    int j = km / cin, c = km % cin;
    const float* tw = tcw + (size_t)blk * HID * HID * 3;   // tw[o][h][j]
    float s = 0.f;
    for (int h = 0; h < HID; ++h)
        s = fmaf(gw[c * HID + h], tw[(o * HID + h) * 3 + j], s);
    M[km * 64 + o] = s;
}

// ---------------- sparse adjacency table: per column v, up to NZMAX (w, k*64) ----------------
__global__ void adjprep_kernel(const float* __restrict__ adj) {
    int v = threadIdx.x;
    if (v >= KP) return;
    int cnt = 0;
    for (int k = 0; k < KP; ++k) {
        float w = adj[k * KP + v];
        if (w != 0.0f && cnt < NZMAX) {
            g_adjT[v * NZMAX + cnt] = make_float2(w, __int_as_float(k * 64));
            ++cnt;
        }
    }
    for (; cnt < NZMAX; ++cnt)
        g_adjT[v * NZMAX + cnt] = make_float2(0.0f, __int_as_float(0));
}

// ---------------- fused STGCN block ----------------
// pre[t,k,o] = sum_j sum_c x[t+(j-1)*DIL, k, c] * M[j*CIN+c][o]   (zero-padded in t)
// out[t,v,o] = relu( (sum_nz w*pre[t,k_nz,o]) * bnInv[o] + bnBeta[o] ) (+ x[t,v,o] if RES)
template <int CIN, int DIL, bool RES>
__global__ void __launch_bounds__(512) stgn_block_kernel(
    const float* __restrict__ xin,
    const float* __restrict__ Mg,
    const float* __restrict__ bns, const float* __restrict__ bnb,
    const float* __restrict__ bnm, const float* __restrict__ bnv,
    float* __restrict__ out)
{
    constexpr int KW = 3 * CIN;                       // folded reduction width
    constexpr int HR = TTILE + 2 * DIL;               // halo time rows
    constexpr int PR = HR * KP;                       // halo positions
    constexpr int XS = (CIN % 4 == 0) ? CIN + 4 : CIN + 1;  // padded X row stride
    constexpr int OP = TTILE * KP;                    // 272 output positions
    constexpr int NQ = OP / 4;                        // 68 row quads

    extern __shared__ float sm[];
    float*  sM = sm;                   // KW*64
    float*  sX = sM + KW * 64;         // PR*XS
    float*  sP = sX + PR * XS;         // OP*64
    float2* sT = (float2*)(sP + OP * 64);  // KP*NZMAX float2

    const int tid = threadIdx.x;
    const int b   = blockIdx.y;
    const int t0  = blockIdx.x * TTILE;

    // --- load weights / sparse adj / halo'd input tile ---
    for (int i = tid; i < KW * 64; i += 512) sM[i] = Mg[i];
    if (tid < KP * NZMAX) sT[tid] = g_adjT[tid];
    {
        const int base_t = t0 - DIL;
        for (int i = tid; i < PR * CIN; i += 512) {
            int pr = i / CIN;          // = h*KP + kk
            int c  = i % CIN;
            int h  = pr / KP;
            int kk = pr % KP;
            int t  = base_t + h;
            float v = 0.f;
            if (t >= 0 && t < TDIM)
                v = xin[((b * TDIM + t) * KP + kk) * CIN + c];
            sX[pr * XS + c] = v;
        }
    }
    __syncthreads();

    // --- GEMM: each thread computes 4 rows x 8 cols per iteration ---
    const int cg = tid & 7;    // column group (8 cols each)
    const int rt = tid >> 3;   // row-quad thread 0..63

    for (int iter = 0; iter < 2; ++iter) {
        int q = rt + 64 * iter;
        if (q >= NQ) break;

        int rowoff[4][3];
#pragma unroll
        for (int i = 0; i < 4; ++i) {
            int p  = 4 * q + i;
            int tt = p / KP, kk = p % KP;
#pragma unroll
            for (int j = 0; j < 3; ++j)
                rowoff[i][j] = ((tt + j * DIL) * KP + kk) * XS;
        }

        if constexpr (CIN % 4 == 0) {
            // f32x2 packed accumulators: 4 rows x 4 column-pairs (8 cols)
            unsigned long long acc2[4][4];
#pragma unroll
            for (int i = 0; i < 4; ++i)
#pragma unroll
                for (int n = 0; n < 4; ++n) acc2[i][n] = 0ULL;

#pragma unroll
            for (int j = 0; j < 3; ++j) {
#pragma unroll 2
                for (int c = 0; c < CIN; c += 4) {
                    float4 a0 = *(const float4*)(sX + rowoff[0][j] + c);
                    float4 a1 = *(const float4*)(sX + rowoff[1][j] + c);
                    float4 a2 = *(const float4*)(sX + rowoff[2][j] + c);
                    float4 a3 = *(const float4*)(sX + rowoff[3][j] + c);
                    const float* ap[4] = {(const float*)&a0, (const float*)&a1,
                                          (const float*)&a2, (const float*)&a3};
#pragma unroll
                    for (int u = 0; u < 4; ++u) {
                        const ulonglong2* mp = (const ulonglong2*)
                            (sM + (j * CIN + c + u) * 64 + (cg << 3));
                        ulonglong2 mA = mp[0];   // cols 0..3 of group (2 pairs)
                        ulonglong2 mB = mp[1];   // cols 4..7 of group (2 pairs)
#pragma unroll
                        for (int i = 0; i < 4; ++i) {
                            unsigned long long ad = pack2_dup(ap[i][u]);
                            fma2(acc2[i][0], ad, mA.x);
                            fma2(acc2[i][1], ad, mA.y);
                            fma2(acc2[i][2], ad, mB.x);
                            fma2(acc2[i][3], ad, mB.y);
                        }
                    }
                }
            }

            // stage pre-graph-mix results to smem
#pragma unroll
            for (int i = 0; i < 4; ++i) {
                float2 p0 = unpack2(acc2[i][0]);
                float2 p1 = unpack2(acc2[i][1]);
                float2 p2 = unpack2(acc2[i][2]);
                float2 p3 = unpack2(acc2[i][3]);
                float* pp = sP + (4 * q + i) * 64 + (cg << 3);
                *(float4*)pp       = make_float4(p0.x, p0.y, p1.x, p1.y);
                *(float4*)(pp + 4) = make_float4(p2.x, p2.y, p3.x, p3.y);
            }
        } else {
            float acc[4][8];
#pragma unroll
            for (int i = 0; i < 4; ++i)
#pragma unroll
                for (int n = 0; n < 8; ++n) acc[i][n] = 0.f;

#pragma unroll
            for (int j = 0; j < 3; ++j) {
                for (int c = 0; c < CIN; ++c) {
                    float av[4];
#pragma unroll
                    for (int i = 0; i < 4; ++i) av[i] = sX[rowoff[i][j] + c];
                    const float* mp = sM + (j * CIN + c) * 64 + (cg << 3);
                    float4 m0 = *(const float4*)mp;
                    float4 m1 = *(const float4*)(mp + 4);
                    const float* mv = (const float*)&m0;
                    const float* mw = (const float*)&m1;
#pragma unroll
                    for (int i = 0; i < 4; ++i) {
#pragma unroll
                        for (int n = 0; n < 4; ++n) {
                            acc[i][n]     = fmaf(av[i], mv[n], acc[i][n]);
                            acc[i][n + 4] = fmaf(av[i], mw[n], acc[i][n + 4]);
                        }
                    }
                }
            }
#pragma unroll
            for (int i = 0; i < 4; ++i) {
                float* pp = sP + (4 * q + i) * 64 + (cg << 3);
                *(float4*)pp       = make_float4(acc[i][0], acc[i][1], acc[i][2], acc[i][3]);
                *(float4*)(pp + 4) = make_float4(acc[i][4], acc[i][5], acc[i][6], acc[i][7]);
            }
        }
    }
    __syncthreads();

    // --- epilogue: SPARSE graph mix over k, BN, ReLU, residual ---
    const int o  = tid & 63;
    const int pg = tid >> 6;   // 0..7
    const float bsv = __ldg(bns + o);
    const float inv = bsv * rsqrtf(__ldg(bnv + o) + 1e-5f);
    const float bet = __ldg(bnb + o) - __ldg(bnm + o) * inv;

    for (int p = pg; p < OP; p += 8) {
        int tt = p / KP, v = p % KP;
        const float* prow = sP + tt * KP * 64 + o;
        float s = 0.f;
#pragma unroll
        for (int e = 0; e < NZMAX; ++e) {
            float2 wt = sT[v * NZMAX + e];
            s = fmaf(wt.x, prow[__float_as_int(wt.y)], s);
        }
        float val = fmaf(s, inv, bet);
        val = fmaxf(val, 0.f);
        int gpos = (b * TDIM + t0 + tt) * KP + v;
        if (RES) val += xin[gpos * CIN + o];
        out[gpos * HID + o] = val;
    }
}

// ---------------- mean pool (stage 1): deterministic slice partials ----------------
__global__ void pool_kernel(const float* __restrict__ x) {
    __shared__ float red[4][64];
    const int b = blockIdx.y, sl = blockIdx.x;
    const int c = threadIdx.x & 63, g = threadIdx.x >> 6;
    const int CH = NPOS / 64;   // 544 positions per slice
    const float* base = x + ((size_t)b * NPOS + sl * CH) * HID;
    float acc = 0.f;
    for (int p = g; p < CH; p += 4)
        acc += base[p * HID + c];
    red[g][c] = acc;
    __syncthreads();
    if (threadIdx.x < 64)
        g_part[(b * 64 + sl) * 64 + c] = red[0][c] + red[1][c] + red[2][c] + red[3][c];
}

// ---------------- pool stage 2 + LayerNorm + FC head ----------------
__global__ void head_kernel(const float* __restrict__ lns, const float* __restrict__ lnb,
                            const float* __restrict__ fw,  const float* __restrict__ fb,
                            float* __restrict__ outp) {
    __shared__ float f[64];
    __shared__ float mu_s, rv_s;
    const int b = blockIdx.x, tid = threadIdx.x;   // 64 threads

    float s = 0.f;
    for (int sl = 0; sl < 64; ++sl)
        s += g_part[(b * 64 + sl) * 64 + tid];
    float v = s * (1.0f / (float)NPOS);
    f[tid] = v;
    __syncthreads();
    if (tid == 0) {
        float m = 0.f;
        for (int i = 0; i < 64; ++i) m += f[i];
        m *= (1.0f / 64.0f);
        float va = 0.f;
        for (int i = 0; i < 64; ++i) { float d = f[i] - m; va = fmaf(d, d, va); }
        va *= (1.0f / 64.0f);
        mu_s = m;
        rv_s = rsqrtf(va + 1e-5f);
    }
    __syncthreads();
    float nf = (v - mu_s) * rv_s * lns[tid] + lnb[tid];
    __syncthreads();
    f[tid] = nf;
    __syncthreads();
    if (tid < 10) {
        float o = fb[tid];
        for (int c = 0; c < 64; ++c)
            o = fmaf(f[c], fw[c * 10 + tid], o);
        outp[b * 10 + tid] = o;
    }
}

// ---------------- launch ----------------
extern "C" void kernel_launch(void* const* d_in, const int* in_sizes, int n_in,
                              void* d_out, int out_size) {
    const float* kpts = (const float*)d_in[0];
    const float* adj  = (const float*)d_in[1];
    const float* gw0  = (const float*)d_in[2];
    const float* gw1  = (const float*)d_in[3];
    const float* gw2  = (const float*)d_in[4];
    const float* tcw  = (const float*)d_in[5];
    const float* bns  = (const float*)d_in[6];
    const float* bnb  = (const float*)d_in[7];
    const float* bnm  = (const float*)d_in[8];
    const float* bnv  = (const float*)d_in[9];
    const float* lns  = (const float*)d_in[10];
    const float* lnb  = (const float*)d_in[11];
    const float* fw   = (const float*)d_in[12];
    const float* fb   = (const float*)d_in[13];
    float* outp = (float*)d_out;

    float *bufA, *bufB, *M0, *M1, *M2;
    cudaGetSymbolAddress((void**)&bufA, g_bufA);
    cudaGetSymbolAddress((void**)&bufB, g_bufB);
    cudaGetSymbolAddress((void**)&M0, g_M0);
    cudaGetSymbolAddress((void**)&M1, g_M1);
    cudaGetSymbolAddress((void**)&M2, g_M2);

    // dynamic smem sizes (floats): M + X(padded) + P + adjT
    const size_t smem0 = (size_t)(9 * 64   + 306 * 4  + 272 * 64 + 2 * KP * NZMAX) * 4;
    const size_t smem1 = (size_t)(192 * 64 + 306 * 68 + 272 * 64 + 2 * KP * NZMAX) * 4;
    const size_t smem2 = (size_t)(192 * 64 + 340 * 68 + 272 * 64 + 2 * KP * NZMAX) * 4;
    cudaFuncSetAttribute(stgn_block_kernel<3, 1, false>,
                         cudaFuncAttributeMaxDynamicSharedMemorySize, (int)smem0);
    cudaFuncSetAttribute(stgn_block_kernel<64, 1, true>,
                         cudaFuncAttributeMaxDynamicSharedMemorySize, (int)smem1);
    cudaFuncSetAttribute(stgn_block_kernel<64, 2, true>,
                         cudaFuncAttributeMaxDynamicSharedMemorySize, (int)smem2);

    prep_kernel<<<(25152 + 255) / 256, 256>>>(gw0, gw1, gw2, tcw);
    adjprep_kernel<<<1, 32>>>(adj);

    dim3 grid(TDIM / TTILE, BATCH);   // 128 x 32
    stgn_block_kernel<3, 1, false><<<grid, 512, smem0>>>(
        kpts, M0, bns + 0,  bnb + 0,  bnm + 0,  bnv + 0,  bufA);
    stgn_block_kernel<64, 1, true><<<grid, 512, smem1>>>(
        bufA, M1, bns + 64, bnb + 64, bnm + 64, bnv + 64, bufB);
    stgn_block_kernel<64, 2, true><<<grid, 512, smem2>>>(
        bufB, M2, bns + 128, bnb + 128, bnm + 128, bnv + 128, bufA);

    pool_kernel<<<dim3(64, BATCH), 256>>>(bufA);
    head_kernel<<<BATCH, 64>>>(lns, lnb, fw, fb, outp);
}

// round 4
// speedup vs baseline: 1.8348x; 1.3808x over previous
#include <cuda_runtime.h>

// ---------------- problem constants ----------------
#define BATCH 32
#define TDIM  2048
#define KP    17
#define HID   64
#define NPOS  (TDIM * KP)   // 34816
#define TT    16            // time steps per CTA
#define NZ    5             // padded nonzeros per adjacency column

typedef unsigned long long ull;

// ---------------- device scratch ----------------
__device__ float g_bufA[(size_t)BATCH * TDIM * KP * HID];
__device__ float g_bufB[(size_t)BATCH * TDIM * KP * HID];
__device__ float g_M0[9 * 64];
__device__ float g_M1[192 * 64];
__device__ float g_M2[192 * 64];
__device__ float2 g_adjT[KP * NZ];    // {w, bitcast(k*64)} for HID-stride gathers
__device__ float2 g_adjT0[KP * NZ];   // {w, bitcast(k*3)}  for kpts gathers
__device__ float g_part2[(size_t)BATCH * 128 * 64];  // per-CTA pool partials

// ---------------- f32x2 helpers ----------------
__device__ __forceinline__ ull pack2_dup(float x) {
    ull r; unsigned int xb = __float_as_uint(x);
    asm("mov.b64 %0, {%1, %1};" : "=l"(r) : "r"(xb));
    return r;
}
__device__ __forceinline__ void fma2(ull& c, ull a, ull b) {
    asm("fma.rn.f32x2 %0, %1, %2, %3;" : "=l"(c) : "l"(a), "l"(b), "l"(c));
}
__device__ __forceinline__ float2 unpack2(ull v) {
    unsigned int lo, hi;
    asm("mov.b64 {%0, %1}, %2;" : "=r"(lo), "=r"(hi) : "l"(v));
    return make_float2(__uint_as_float(lo), __uint_as_float(hi));
}

// ---------------- weight folding: M[j*CIN+c][o] = sum_h gw[c][h]*tw[o][h][j] ----------------
__global__ void prep_kernel(const float* __restrict__ gw0,
                            const float* __restrict__ gw1,
                            const float* __restrict__ gw2,
                            const float* __restrict__ tcw) {
    int id = blockIdx.x * blockDim.x + threadIdx.x;
    const int n0 = 9 * 64, n1 = 192 * 64, n2 = 192 * 64;
    if (id >= n0 + n1 + n2) return;
    int blk, cin, e; const float* gw; float* M;
    if (id < n0)            { blk = 0; cin = 3;  gw = gw0; M = g_M0; e = id; }
    else if (id < n0 + n1)  { blk = 1; cin = 64; gw = gw1; M = g_M1; e = id - n0; }
    else                    { blk = 2; cin = 64; gw = gw2; M = g_M2; e = id - n0 - n1; }
    int km = e / 64, o = e % 64;
    int j = km / cin, c = km % cin;
    const float* tw = tcw + (size_t)blk * HID * HID * 3;
    float s = 0.f;
    for (int h = 0; h < HID; ++h)
        s = fmaf(gw[c * HID + h], tw[(o * HID + h) * 3 + j], s);
    M[km * 64 + o] = s;
}

// ---------------- sparse adjacency tables ----------------
__global__ void adjprep_kernel(const float* __restrict__ adj) {
    int v = threadIdx.x;
    if (v >= KP) return;
    int cnt = 0;
    for (int k = 0; k < KP; ++k) {
        float w = adj[k * KP + v];
        if (w != 0.0f && cnt < NZ) {
            g_adjT [v * NZ + cnt] = make_float2(w, __int_as_float(k * 64));
            g_adjT0[v * NZ + cnt] = make_float2(w, __int_as_float(k * 3));
            ++cnt;
        }
    }
    for (; cnt < NZ; ++cnt) {
        g_adjT [v * NZ + cnt] = make_float2(0.0f, __int_as_float(0));
        g_adjT0[v * NZ + cnt] = make_float2(0.0f, __int_as_float(0));
    }
}

// ---------------- block 0 (CIN=3, DIL=1, no residual) ----------------
__global__ void __launch_bounds__(512) blk0_kernel(
    const float* __restrict__ kpts,
    const float* __restrict__ bns, const float* __restrict__ bnb,
    const float* __restrict__ bnm, const float* __restrict__ bnv,
    float* __restrict__ out)
{
    constexpr int PR = (TT + 2) * KP;   // 306
    __shared__ float  sM0[9 * 64];
    __shared__ ull    sZ[PR * 4];
    __shared__ float  sBN[128];
    __shared__ float2 sT[KP * NZ];

    const int tid = threadIdx.x;
    const int b   = blockIdx.y;
    const int t0  = blockIdx.x * TT;

    for (int i = tid; i < 9 * 64; i += 512) sM0[i] = g_M0[i];
    if (tid < KP * NZ) sT[tid] = g_adjT0[tid];
    if (tid < 64) {
        float inv = __ldg(bns + tid) * rsqrtf(__ldg(bnv + tid) + 1e-5f);
        sBN[tid] = inv;
        sBN[64 + tid] = __ldg(bnb + tid) - __ldg(bnm + tid) * inv;
    }
    __syncthreads();

    // Z build: z[ph][c] = adj-mix of kpts, duplicated pairs
    for (int idx = tid; idx < PR * 3; idx += 512) {
        int ph = idx / 3, c = idx - ph * 3;
        int h = ph / KP, kk = ph - h * KP;
        int t = t0 - 1 + h;
        float v = 0.f;
        if ((unsigned)t < (unsigned)TDIM) {
            const float* xr = kpts + (size_t)(b * TDIM + t) * (KP * 3);
#pragma unroll
            for (int e = 0; e < NZ; ++e) {
                float2 wt = sT[kk * NZ + e];
                v = fmaf(wt.x, xr[__float_as_int(wt.y) + c], v);
            }
        }
        sZ[ph * 4 + c] = pack2_dup(v);
    }
    __syncthreads();

    const int cg = tid & 7, rt = tid >> 3;
    const int o1 = cg * 4, o2 = 32 + o1;
    const size_t gb = (size_t)(b * TDIM + t0) * KP;
    const float4 invA = *(const float4*)(sBN + o1);
    const float4 invB = *(const float4*)(sBN + o2);
    const float4 betA = *(const float4*)(sBN + 64 + o1);
    const float4 betB = *(const float4*)(sBN + 64 + o2);

    for (int it = 0; it < 2; ++it) {
        bool act = (it == 0) || (tid < 32);
        if (!act) continue;
        const int prow = (it ? 64 + rt : rt);   // rows prow + 68*i

        ull acc[4][4] = {};
#pragma unroll
        for (int j = 0; j < 3; ++j) {
            const ull* zb = sZ + (prow + j * KP) * 4;
#pragma unroll
            for (int c = 0; c < 3; ++c) {
                const float* mk = sM0 + (j * 3 + c) * 64;
                ulonglong2 m1 = *(const ulonglong2*)(mk + o1);
                ulonglong2 m2 = *(const ulonglong2*)(mk + o2);
#pragma unroll
                for (int i = 0; i < 4; ++i) {
                    ull av = zb[i * 68 * 4 + c];
                    fma2(acc[i][0], av, m1.x); fma2(acc[i][1], av, m1.y);
                    fma2(acc[i][2], av, m2.x); fma2(acc[i][3], av, m2.y);
                }
            }
        }
#pragma unroll
        for (int i = 0; i < 4; ++i) {
            float2 q0 = unpack2(acc[i][0]), q1 = unpack2(acc[i][1]);
            float2 q2 = unpack2(acc[i][2]), q3 = unpack2(acc[i][3]);
            size_t rowo = (gb + prow + 68 * i) * 64;
            float4 v1, v2;
            v1.x = fmaxf(fmaf(q0.x, invA.x, betA.x), 0.f);
            v1.y = fmaxf(fmaf(q0.y, invA.y, betA.y), 0.f);
            v1.z = fmaxf(fmaf(q1.x, invA.z, betA.z), 0.f);
            v1.w = fmaxf(fmaf(q1.y, invA.w, betA.w), 0.f);
            v2.x = fmaxf(fmaf(q2.x, invB.x, betB.x), 0.f);
            v2.y = fmaxf(fmaf(q2.y, invB.y, betB.y), 0.f);
            v2.z = fmaxf(fmaf(q3.x, invB.z, betB.z), 0.f);
            v2.w = fmaxf(fmaf(q3.y, invB.w, betB.w), 0.f);
            *(float4*)(out + rowo + o1) = v1;
            *(float4*)(out + rowo + o2) = v2;
        }
    }
}

// ---------------- blocks 1 & 2 (CIN=64, residual; POOL => emit pool partials) ----------------
template <int DIL, bool POOL>
__global__ void __launch_bounds__(512) blk12_kernel(
    const float* __restrict__ xin,
    const float* __restrict__ Mg,
    const float* __restrict__ bns, const float* __restrict__ bnb,
    const float* __restrict__ bnm, const float* __restrict__ bnv,
    float* __restrict__ outp)
{
    constexpr int PR = (TT + 2 * DIL) * KP;   // 306 / 340
    constexpr int ZS = 66;                    // ull stride per Z row
    extern __shared__ char smem[];
    float*  sM  = (float*)smem;                               // 12288 floats
    ull*    sZ  = (ull*)(smem + 49152);                       // PR*66 ull
    float*  sBN = (float*)(smem + 49152 + PR * ZS * 8);       // 128 floats
    float2* sT  = (float2*)(smem + 49152 + PR * ZS * 8 + 512);// 85 float2

    const int tid = threadIdx.x;
    const int b   = blockIdx.y;
    const int t0  = blockIdx.x * TT;

    if (tid < KP * NZ) sT[tid] = g_adjT[tid];
    if (tid < 64) {
        float inv = __ldg(bns + tid) * rsqrtf(__ldg(bnv + tid) + 1e-5f);
        sBN[tid] = inv;
        sBN[64 + tid] = __ldg(bnb + tid) - __ldg(bnm + tid) * inv;
    }
    __syncthreads();

    // weight tile
    {
        const float4* src = (const float4*)Mg;
        float4* dst = (float4*)sM;
        for (int i = tid; i < 3072; i += 512) dst[i] = src[i];
    }
    // Z build: z[ph][c] = adj-mix of xin row, duplicated pairs
    for (int idx = tid; idx < PR * 16; idx += 512) {
        int ph = idx >> 4, c4 = idx & 15;
        int h = ph / KP, kk = ph - h * KP;
        int t = t0 - DIL + h;
        float4 v = make_float4(0.f, 0.f, 0.f, 0.f);
        if ((unsigned)t < (unsigned)TDIM) {
            const float* xr = xin + (size_t)(b * TDIM + t) * (KP * HID) + c4 * 4;
#pragma unroll
            for (int e = 0; e < NZ; ++e) {
                float2 wt = sT[kk * NZ + e];
                const float4 xa = *(const float4*)(xr + __float_as_int(wt.y));
                v.x = fmaf(wt.x, xa.x, v.x);
                v.y = fmaf(wt.x, xa.y, v.y);
                v.z = fmaf(wt.x, xa.z, v.z);
                v.w = fmaf(wt.x, xa.w, v.w);
            }
        }
        ull* zp = sZ + ph * ZS + c4 * 4;
        ulonglong2 z01, z23;
        z01.x = pack2_dup(v.x); z01.y = pack2_dup(v.y);
        z23.x = pack2_dup(v.z); z23.y = pack2_dup(v.w);
        *(ulonglong2*)zp       = z01;
        *(ulonglong2*)(zp + 2) = z23;
    }
    __syncthreads();

    const int cg = tid & 7, rt = tid >> 3;
    const int o1 = cg * 4, o2 = 32 + o1;
    const size_t gb = (size_t)(b * TDIM + t0) * KP;
    float ps[8] = {0.f, 0.f, 0.f, 0.f, 0.f, 0.f, 0.f, 0.f};

    for (int it = 0; it < 2; ++it) {
        bool act = (it == 0) || (tid < 32);
        if (act) {
            const int prow = (it ? 64 + rt : rt);   // rows prow + 68*i

            ull acc[4][4] = {};
#pragma unroll
            for (int j = 0; j < 3; ++j) {
                const ull* zb = sZ + (prow + j * DIL * KP) * ZS;
#pragma unroll 2
                for (int c4 = 0; c4 < 16; ++c4) {
                    const int cu = c4 * 4;
                    ulonglong2 aA[4], aB[4];
#pragma unroll
                    for (int i = 0; i < 4; ++i) {
                        const ull* zr = zb + i * (68 * ZS) + cu;
                        aA[i] = *(const ulonglong2*)zr;
                        aB[i] = *(const ulonglong2*)(zr + 2);
                    }
                    const float* mj = sM + (j * 64 + cu) * 64;
#pragma unroll
                    for (int u = 0; u < 4; ++u) {
                        ulonglong2 m1 = *(const ulonglong2*)(mj + u * 64 + o1);
                        ulonglong2 m2 = *(const ulonglong2*)(mj + u * 64 + o2);
#pragma unroll
                        for (int i = 0; i < 4; ++i) {
                            ull av = (u < 2) ? (u == 0 ? aA[i].x : aA[i].y)
                                             : (u == 2 ? aB[i].x : aB[i].y);
                            fma2(acc[i][0], av, m1.x); fma2(acc[i][1], av, m1.y);
                            fma2(acc[i][2], av, m2.x); fma2(acc[i][3], av, m2.y);
                        }
                    }
                }
            }

            const float4 invA = *(const float4*)(sBN + o1);
            const float4 invB = *(const float4*)(sBN + o2);
            const float4 betA = *(const float4*)(sBN + 64 + o1);
            const float4 betB = *(const float4*)(sBN + 64 + o2);
#pragma unroll
            for (int i = 0; i < 4; ++i) {
                float2 q0 = unpack2(acc[i][0]), q1 = unpack2(acc[i][1]);
                float2 q2 = unpack2(acc[i][2]), q3 = unpack2(acc[i][3]);
                size_t rowo = (gb + prow + 68 * i) * 64;
                float4 r1 = *(const float4*)(xin + rowo + o1);
                float4 r2 = *(const float4*)(xin + rowo + o2);
                float4 v1, v2;
                v1.x = fmaxf(fmaf(q0.x, invA.x, betA.x), 0.f) + r1.x;
                v1.y = fmaxf(fmaf(q0.y, invA.y, betA.y), 0.f) + r1.y;
                v1.z = fmaxf(fmaf(q1.x, invA.z, betA.z), 0.f) + r1.z;
                v1.w = fmaxf(fmaf(q1.y, invA.w, betA.w), 0.f) + r1.w;
                v2.x = fmaxf(fmaf(q2.x, invB.x, betB.x), 0.f) + r2.x;
                v2.y = fmaxf(fmaf(q2.y, invB.y, betB.y), 0.f) + r2.y;
                v2.z = fmaxf(fmaf(q3.x, invB.z, betB.z), 0.f) + r2.z;
                v2.w = fmaxf(fmaf(q3.y, invB.w, betB.w), 0.f) + r2.w;
                if (POOL) {
                    ps[0] += v1.x; ps[1] += v1.y; ps[2] += v1.z; ps[3] += v1.w;
                    ps[4] += v2.x; ps[5] += v2.y; ps[6] += v2.z; ps[7] += v2.w;
                } else {
                    *(float4*)(outp + rowo + o1) = v1;
                    *(float4*)(outp + rowo + o2) = v2;
                }
            }
        }
    }

    if (POOL) {
        __syncthreads();                     // everyone done reading sM
        float* sRed = (float*)smem;          // alias weight tile (16 KB)
        *(float4*)(sRed + tid * 8)     = make_float4(ps[0], ps[1], ps[2], ps[3]);
        *(float4*)(sRed + tid * 8 + 4) = make_float4(ps[4], ps[5], ps[6], ps[7]);
        __syncthreads();
        if (tid < 64) {
            int quad = tid >> 5, cgq = (tid & 31) >> 2, li = tid & 3;
            float s = 0.f;
            for (int rg = 0; rg < 64; ++rg)
                s += sRed[(rg * 8 + cgq) * 8 + quad * 4 + li];
            outp[((size_t)b * 128 + blockIdx.x) * 64 + tid] = s;
        }
    }
}

// ---------------- pool stage 2 + LayerNorm + FC head ----------------
__global__ void head_kernel(const float* __restrict__ lns, const float* __restrict__ lnb,
                            const float* __restrict__ fw,  const float* __restrict__ fb,
                            const float* __restrict__ part, float* __restrict__ outp) {
    __shared__ float f[64];
    __shared__ float mu_s, rv_s;
    const int b = blockIdx.x, tid = threadIdx.x;   // 64 threads

    float s = 0.f;
    for (int i = 0; i < 128; ++i)
        s += part[((size_t)b * 128 + i) * 64 + tid];
    float v = s * (1.0f / (float)NPOS);
    f[tid] = v;
    __syncthreads();
    if (tid == 0) {
        float m = 0.f;
        for (int i = 0; i < 64; ++i) m += f[i];
        m *= (1.0f / 64.0f);
        float va = 0.f;
        for (int i = 0; i < 64; ++i) { float d = f[i] - m; va = fmaf(d, d, va); }
        va *= (1.0f / 64.0f);
        mu_s = m;
        rv_s = rsqrtf(va + 1e-5f);
    }
    __syncthreads();
    float nf = (v - mu_s) * rv_s * lns[tid] + lnb[tid];
    __syncthreads();
    f[tid] = nf;
    __syncthreads();
    if (tid < 10) {
        float o = fb[tid];
        for (int c = 0; c < 64; ++c)
            o = fmaf(f[c], fw[c * 10 + tid], o);
        outp[b * 10 + tid] = o;
    }
}

// ---------------- launch ----------------
extern "C" void kernel_launch(void* const* d_in, const int* in_sizes, int n_in,
                              void* d_out, int out_size) {
    const float* kpts = (const float*)d_in[0];
    const float* adj  = (const float*)d_in[1];
    const float* gw0  = (const float*)d_in[2];
    const float* gw1  = (const float*)d_in[3];
    const float* gw2  = (const float*)d_in[4];
    const float* tcw  = (const float*)d_in[5];
    const float* bns  = (const float*)d_in[6];
    const float* bnb  = (const float*)d_in[7];
    const float* bnm  = (const float*)d_in[8];
    const float* bnv  = (const float*)d_in[9];
    const float* lns  = (const float*)d_in[10];
    const float* lnb  = (const float*)d_in[11];
    const float* fw   = (const float*)d_in[12];
    const float* fb   = (const float*)d_in[13];
    float* outp = (float*)d_out;

    float *bufA, *bufB, *M1, *M2, *part;
    cudaGetSymbolAddress((void**)&bufA, g_bufA);
    cudaGetSymbolAddress((void**)&bufB, g_bufB);
    cudaGetSymbolAddress((void**)&M1, g_M1);
    cudaGetSymbolAddress((void**)&M2, g_M2);
    cudaGetSymbolAddress((void**)&part, g_part2);

    // dynamic smem: weights 49152 + Z (PR*66*8) + BN 512 + adjT 680
    const size_t smem1 = 49152 + (size_t)(16 + 2) * KP * 66 * 8 + 512 + 680;  // 211912
    const size_t smem2 = 49152 + (size_t)(16 + 4) * KP * 66 * 8 + 512 + 680;  // 229864
    cudaFuncSetAttribute(blk12_kernel<1, false>,
                         cudaFuncAttributeMaxDynamicSharedMemorySize, (int)smem1);
    cudaFuncSetAttribute(blk12_kernel<2, true>,
                         cudaFuncAttributeMaxDynamicSharedMemorySize, (int)smem2);

    prep_kernel<<<(25152 + 255) / 256, 256>>>(gw0, gw1, gw2, tcw);
    adjprep_kernel<<<1, 32>>>(adj);

    dim3 grid(TDIM / TT, BATCH);   // 128 x 32
    blk0_kernel<<<grid, 512>>>(kpts, bns, bnb, bnm, bnv, bufA);
    blk12_kernel<1, false><<<grid, 512, smem1>>>(
        bufA, M1, bns + 64,  bnb + 64,  bnm + 64,  bnv + 64,  bufB);
    blk12_kernel<2, true><<<grid, 512, smem2>>>(
        bufB, M2, bns + 128, bnb + 128, bnm + 128, bnv + 128, part);

    head_kernel<<<BATCH, 64>>>(lns, lnb, fw, fb, part, outp);
}

// round 6
// speedup vs baseline: 4.0250x; 2.1937x over previous
#include <cuda_runtime.h>

// ---------------- problem constants ----------------
#define BATCH 32
#define TDIM  2048
#define KP    17
#define HID   64
#define NPOS  (TDIM * KP)   // 34816
#define TT    16            // blk0 time tile
#define TT2   32            // layer kernel time tile
#define NZ    5

typedef unsigned long long ull;
typedef unsigned int u32;

// ---------------- device scratch ----------------
__device__ float g_bufA[(size_t)BATCH * NPOS * HID];
__device__ float g_bufB[(size_t)BATCH * NPOS * HID];
__device__ float g_M0[9 * 64];          // blk0 folded weights (fp32)
__device__ float g_MT1[64 * 192];       // layer1 B: [out_ch][k] tf32-rounded
__device__ float g_MT2[64 * 192];       // layer2 B
__device__ float2 g_adjT[KP * NZ];      // {w, bitcast(k*64)}
__device__ float2 g_adjT0[KP * NZ];     // {w, bitcast(k*3)}
__device__ float g_part[(size_t)BATCH * 64 * 64];   // pool partials [b][ctaX][c]

// ---------------- helpers ----------------
__device__ __forceinline__ ull pack2_dup(float x) {
    ull r; u32 xb = __float_as_uint(x);
    asm("mov.b64 %0, {%1, %1};" : "=l"(r) : "r"(xb));
    return r;
}
__device__ __forceinline__ void fma2(ull& c, ull a, ull b) {
    asm("fma.rn.f32x2 %0, %1, %2, %3;" : "=l"(c) : "l"(a), "l"(b), "l"(c));
}
__device__ __forceinline__ float2 unpack2(ull v) {
    u32 lo, hi;
    asm("mov.b64 {%0, %1}, %2;" : "=r"(lo), "=r"(hi) : "l"(v));
    return make_float2(__uint_as_float(lo), __uint_as_float(hi));
}
__device__ __forceinline__ u32 f2tf(float f) {
    u32 u; asm("cvt.rna.tf32.f32 %0, %1;" : "=r"(u) : "f"(f)); return u;
}
__device__ __forceinline__ void mma_tf32(float* c, const u32* a, const u32* b) {
    asm volatile(
        "mma.sync.aligned.m16n8k8.row.col.f32.tf32.tf32.f32 "
        "{%0,%1,%2,%3}, {%4,%5,%6,%7}, {%8,%9}, {%0,%1,%2,%3};"
        : "+f"(c[0]), "+f"(c[1]), "+f"(c[2]), "+f"(c[3])
        : "r"(a[0]), "r"(a[1]), "r"(a[2]), "r"(a[3]), "r"(b[0]), "r"(b[1]));
}

// ---------------- weight folding ----------------
__global__ void prep_kernel(const float* __restrict__ gw0,
                            const float* __restrict__ gw1,
                            const float* __restrict__ gw2,
                            const float* __restrict__ tcw) {
    int id = blockIdx.x * blockDim.x + threadIdx.x;
    const int n0 = 9 * 64, n1 = 192 * 64;
    if (id >= n0 + 2 * n1) return;
    int blk, cin, e; const float* gw;
    if (id < n0)           { blk = 0; cin = 3;  gw = gw0; e = id; }
    else if (id < n0 + n1) { blk = 1; cin = 64; gw = gw1; e = id - n0; }
    else                   { blk = 2; cin = 64; gw = gw2; e = id - n0 - n1; }
    int km = e / 64, o = e % 64;
    int j = km / cin, c = km % cin;
    const float* tw = tcw + (size_t)blk * HID * HID * 3;
    float s = 0.f;
    for (int h = 0; h < HID; ++h)
        s = fmaf(gw[c * HID + h], tw[(o * HID + h) * 3 + j], s);
    if (blk == 0) g_M0[km * 64 + o] = s;
    else {
        float* MT = (blk == 1) ? g_MT1 : g_MT2;
        MT[o * 192 + km] = __uint_as_float(f2tf(s));
    }
}

__global__ void adjprep_kernel(const float* __restrict__ adj) {
    int v = threadIdx.x;
    if (v >= KP) return;
    int cnt = 0;
    for (int k = 0; k < KP; ++k) {
        float w = adj[k * KP + v];
        if (w != 0.0f && cnt < NZ) {
            g_adjT [v * NZ + cnt] = make_float2(w, __int_as_float(k * 64));
            g_adjT0[v * NZ + cnt] = make_float2(w, __int_as_float(k * 3));
            ++cnt;
        }
    }
    for (; cnt < NZ; ++cnt) {
        g_adjT [v * NZ + cnt] = make_float2(0.0f, __int_as_float(0));
        g_adjT0[v * NZ + cnt] = make_float2(0.0f, __int_as_float(0));
    }
}

// ---------------- block 0 (fp32 FFMA2 path, CIN=3) ----------------
__global__ void __launch_bounds__(512) blk0_kernel(
    const float* __restrict__ kpts,
    const float* __restrict__ bns, const float* __restrict__ bnb,
    const float* __restrict__ bnm, const float* __restrict__ bnv,
    float* __restrict__ out)
{
    constexpr int PR = (TT + 2) * KP;   // 306
    __shared__ float  sM0[9 * 64];
    __shared__ ull    sZ[PR * 4];
    __shared__ float  sBN[128];
    __shared__ float2 sT[KP * NZ];

    const int tid = threadIdx.x;
    const int b   = blockIdx.y;
    const int t0  = blockIdx.x * TT;

    for (int i = tid; i < 9 * 64; i += 512) sM0[i] = g_M0[i];
    if (tid < KP * NZ) sT[tid] = g_adjT0[tid];
    if (tid < 64) {
        float inv = __ldg(bns + tid) * rsqrtf(__ldg(bnv + tid) + 1e-5f);
        sBN[tid] = inv;
        sBN[64 + tid] = __ldg(bnb + tid) - __ldg(bnm + tid) * inv;
    }
    __syncthreads();

    for (int idx = tid; idx < PR * 3; idx += 512) {
        int ph = idx / 3, c = idx - ph * 3;
        int h = ph / KP, kk = ph - h * KP;
        int t = t0 - 1 + h;
        float v = 0.f;
        if ((unsigned)t < (unsigned)TDIM) {
            const float* xr = kpts + (size_t)(b * TDIM + t) * (KP * 3);
#pragma unroll
            for (int e = 0; e < NZ; ++e) {
                float2 wt = sT[kk * NZ + e];
                v = fmaf(wt.x, xr[__float_as_int(wt.y) + c], v);
            }
        }
        sZ[ph * 4 + c] = pack2_dup(v);
    }
    __syncthreads();

    const int cg = tid & 7, rt = tid >> 3;
    const int o1 = cg * 4, o2 = 32 + o1;
    const size_t gb = (size_t)(b * TDIM + t0) * KP;
    const float4 invA = *(const float4*)(sBN + o1);
    const float4 invB = *(const float4*)(sBN + o2);
    const float4 betA = *(const float4*)(sBN + 64 + o1);
    const float4 betB = *(const float4*)(sBN + 64 + o2);

    for (int it = 0; it < 2; ++it) {
        bool act = (it == 0) || (tid < 32);
        if (!act) continue;
        const int prow = (it ? 64 + rt : rt);

        ull acc[4][4] = {};
#pragma unroll
        for (int j = 0; j < 3; ++j) {
            const ull* zb = sZ + (prow + j * KP) * 4;
#pragma unroll
            for (int c = 0; c < 3; ++c) {
                const float* mk = sM0 + (j * 3 + c) * 64;
                ulonglong2 m1 = *(const ulonglong2*)(mk + o1);
                ulonglong2 m2 = *(const ulonglong2*)(mk + o2);
#pragma unroll
                for (int i = 0; i < 4; ++i) {
                    ull av = zb[i * 68 * 4 + c];
                    fma2(acc[i][0], av, m1.x); fma2(acc[i][1], av, m1.y);
                    fma2(acc[i][2], av, m2.x); fma2(acc[i][3], av, m2.y);
                }
            }
        }
#pragma unroll
        for (int i = 0; i < 4; ++i) {
            float2 q0 = unpack2(acc[i][0]), q1 = unpack2(acc[i][1]);
            float2 q2 = unpack2(acc[i][2]), q3 = unpack2(acc[i][3]);
            size_t rowo = (gb + prow + 68 * i) * 64;
            float4 v1, v2;
            v1.x = fmaxf(fmaf(q0.x, invA.x, betA.x), 0.f);
            v1.y = fmaxf(fmaf(q0.y, invA.y, betA.y), 0.f);
            v1.z = fmaxf(fmaf(q1.x, invA.z, betA.z), 0.f);
            v1.w = fmaxf(fmaf(q1.y, invA.w, betA.w), 0.f);
            v2.x = fmaxf(fmaf(q2.x, invB.x, betB.x), 0.f);
            v2.y = fmaxf(fmaf(q2.y, invB.y, betB.y), 0.f);
            v2.z = fmaxf(fmaf(q3.x, invB.z, betB.z), 0.f);
            v2.w = fmaxf(fmaf(q3.y, invB.w, betB.w), 0.f);
            *(float4*)(out + rowo + o1) = v1;
            *(float4*)(out + rowo + o2) = v2;
        }
    }
}

// ---------------- layers 1 & 2: fused adj-premix + tf32 mma.sync GEMM ----------------
// A slab (smem): halo'd premixed rows [RA][68] tf32. B slab: [64][196] tf32.
// out = relu(BN(sum_j A_j @ B_j)) + resid ; POOL: accumulate channel sums instead.
template <int DIL, bool POOL>
__global__ void __launch_bounds__(512) layer_kernel(
    const float* __restrict__ Y,            // input (also residual), compact [NPOS][64]
    const float* __restrict__ MT,           // [64][192] tf32 weights
    const float* __restrict__ bns, const float* __restrict__ bnb,
    const float* __restrict__ bnm, const float* __restrict__ bnv,
    float* __restrict__ outp)               // compact out, or pool partials if POOL
{
    constexpr int RA   = (TT2 + 2 * DIL) * KP;   // 578 / 612 halo rows
    constexpr int ZS   = 68;                     // A row stride (floats)
    constexpr int NSH  = KP * DIL;               // row shift per tap
    constexpr int OFF_B   = RA * ZS;             // floats
    constexpr int OFF_INV = OFF_B + 64 * 196;
    constexpr int OFF_BET = OFF_INV + 64;
    constexpr int OFF_T   = OFF_BET + 64;        // 85 float2 = 170 floats
    constexpr int OFF_PL  = OFF_T + 170;         // 16*64 pool scratch

    extern __shared__ float sm[];
    u32*    sZu  = (u32*)sm;
    u32*    sBu  = (u32*)(sm + OFF_B);
    float*  sInv = sm + OFF_INV;
    float*  sBet = sm + OFF_BET;
    float2* sT   = (float2*)(sm + OFF_T);
    float*  sPl  = sm + OFF_PL;

    const int tid = threadIdx.x;
    const int wid = tid >> 5, lid = tid & 31;
    const int g = lid >> 2, tig = lid & 3;
    const int b = blockIdx.y;
    const int t0 = blockIdx.x * TT2;
    const float* Yb = Y + (size_t)b * NPOS * 64;

    if (tid < KP * NZ) sT[tid] = g_adjT[tid];
    if (tid < 64) {
        float inv = __ldg(bns + tid) * rsqrtf(__ldg(bnv + tid) + 1e-5f);
        sInv[tid] = inv;
        sBet[tid] = __ldg(bnb + tid) - __ldg(bnm + tid) * inv;
    }
    // B slab: [o][196] tf32 (already rounded in prep)
    for (int idx = tid; idx < 64 * 48; idx += 512) {
        int r = idx / 48, c4 = idx - r * 48;
        *(uint4*)(sBu + r * 196 + c4 * 4) = *(const uint4*)(MT + r * 192 + c4 * 4);
    }
    __syncthreads();   // sT ready before staging uses it

    // A slab staging: premixed + tf32-rounded halo rows
    for (int idx = tid; idx < RA * 16; idx += 512) {
        int zr = idx >> 4, c4 = idx & 15;
        int h = zr / KP, kk = zr - h * KP;
        int t = t0 - DIL + h;
        uint4 o = make_uint4(0, 0, 0, 0);
        if ((unsigned)t < (unsigned)TDIM) {
            const float* xr = Yb + (size_t)t * (KP * 64) + c4 * 4;
            float4 v = make_float4(0.f, 0.f, 0.f, 0.f);
#pragma unroll
            for (int e = 0; e < NZ; ++e) {
                float2 wt = sT[kk * NZ + e];
                const float4 xa = *(const float4*)(xr + __float_as_int(wt.y));
                v.x = fmaf(wt.x, xa.x, v.x);
                v.y = fmaf(wt.x, xa.y, v.y);
                v.z = fmaf(wt.x, xa.z, v.z);
                v.w = fmaf(wt.x, xa.w, v.w);
            }
            o.x = f2tf(v.x); o.y = f2tf(v.y); o.z = f2tf(v.z); o.w = f2tf(v.w);
        }
        *(uint4*)(sZu + zr * ZS + c4 * 4) = o;
    }
    __syncthreads();

    const size_t gbase = (size_t)(b * NPOS + t0 * KP) * 64;
    float ps[16];
    if (POOL) {
#pragma unroll
        for (int i = 0; i < 16; ++i) ps[i] = 0.f;
    }

    // 34 m16-row tiles; warp w handles w, w+16, (w+32)
    for (int ti = wid; ti < (TT2 * KP) / 16; ti += 16) {
        const int row0 = ti * 16;
        float c[8][4];
#pragma unroll
        for (int i = 0; i < 8; ++i)
#pragma unroll
            for (int n = 0; n < 4; ++n) c[i][n] = 0.f;

#pragma unroll
        for (int tap = 0; tap < 3; ++tap) {
            const u32* za = sZu + (row0 + tap * NSH + g) * ZS + tig;
#pragma unroll
            for (int k8 = 0; k8 < 8; ++k8) {
                u32 a[4];
                const u32* zp = za + k8 * 8;
                a[0] = zp[0];
                a[1] = zp[8 * ZS];
                a[2] = zp[4];
                a[3] = zp[8 * ZS + 4];
                const int kcol = tap * 64 + k8 * 8 + tig;
#pragma unroll
                for (int i = 0; i < 8; ++i) {
                    u32 bf[2];
                    const u32* bp = sBu + (8 * i + g) * 196 + kcol;
                    bf[0] = bp[0];
                    bf[1] = bp[4];
                    mma_tf32(c[i], a, bf);
                }
            }
        }

        // epilogue: BN + ReLU + residual (+ pool)
        const size_t grow = gbase + (size_t)(row0 + g) * 64;
        const float* rp = Y + grow;
        float* op = POOL ? nullptr : (outp + grow);
#pragma unroll
        for (int i = 0; i < 8; ++i) {
            const int ch = 8 * i + 2 * tig;
            const float2 inv = *(const float2*)(sInv + ch);
            const float2 bet = *(const float2*)(sBet + ch);
            const float2 r0v = *(const float2*)(rp + ch);
            const float2 r1v = *(const float2*)(rp + 8 * 64 + ch);
            float v0 = fmaxf(fmaf(c[i][0], inv.x, bet.x), 0.f) + r0v.x;
            float v1 = fmaxf(fmaf(c[i][1], inv.y, bet.y), 0.f) + r0v.y;
            float v2 = fmaxf(fmaf(c[i][2], inv.x, bet.x), 0.f) + r1v.x;
            float v3 = fmaxf(fmaf(c[i][3], inv.y, bet.y), 0.f) + r1v.y;
            if (POOL) {
                ps[2 * i]     += v0 + v2;
                ps[2 * i + 1] += v1 + v3;
            } else {
                *(float2*)(op + ch)          = make_float2(v0, v1);
                *(float2*)(op + 8 * 64 + ch) = make_float2(v2, v3);
            }
        }
    }

    if (POOL) {
        // reduce over g (lane bits 2..4), then across warps
#pragma unroll
        for (int i = 0; i < 16; ++i) {
            ps[i] += __shfl_xor_sync(0xFFFFFFFF, ps[i], 4);
            ps[i] += __shfl_xor_sync(0xFFFFFFFF, ps[i], 8);
            ps[i] += __shfl_xor_sync(0xFFFFFFFF, ps[i], 16);
        }
        if (g == 0) {
#pragma unroll
            for (int i = 0; i < 8; ++i) {
                sPl[wid * 64 + 8 * i + 2 * tig]     = ps[2 * i];
                sPl[wid * 64 + 8 * i + 2 * tig + 1] = ps[2 * i + 1];
            }
        }
        __syncthreads();
        if (tid < 64) {
            float s = 0.f;
            for (int w = 0; w < 16; ++w)
                s += sPl[w * 64 + tid];
            outp[((size_t)b * 64 + blockIdx.x) * 64 + tid] = s;
        }
    }
}

// ---------------- head: pool finish + LN + FC ----------------
__global__ void head_kernel(const float* __restrict__ lns, const float* __restrict__ lnb,
                            const float* __restrict__ fw,  const float* __restrict__ fb,
                            float* __restrict__ outp) {
    __shared__ float f[64];
    __shared__ float mu_s, rv_s;
    const int b = blockIdx.x, tid = threadIdx.x;
    float s = 0.f;
    for (int i = 0; i < 64; ++i)
        s += g_part[((size_t)b * 64 + i) * 64 + tid];
    float v = s * (1.0f / (float)NPOS);
    f[tid] = v;
    __syncthreads();
    if (tid == 0) {
        float m = 0.f;
        for (int i = 0; i < 64; ++i) m += f[i];
        m *= (1.0f / 64.0f);
        float va = 0.f;
        for (int i = 0; i < 64; ++i) { float d = f[i] - m; va = fmaf(d, d, va); }
        va *= (1.0f / 64.0f);
        mu_s = m; rv_s = rsqrtf(va + 1e-5f);
    }
    __syncthreads();
    float nf = (v - mu_s) * rv_s * lns[tid] + lnb[tid];
    __syncthreads();
    f[tid] = nf;
    __syncthreads();
    if (tid < 10) {
        float o = fb[tid];
        for (int c = 0; c < 64; ++c)
            o = fmaf(f[c], fw[c * 10 + tid], o);
        outp[b * 10 + tid] = o;
    }
}

// ---------------- launch ----------------
extern "C" void kernel_launch(void* const* d_in, const int* in_sizes, int n_in,
                              void* d_out, int out_size) {
    const float* kpts = (const float*)d_in[0];
    const float* adj  = (const float*)d_in[1];
    const float* gw0  = (const float*)d_in[2];
    const float* gw1  = (const float*)d_in[3];
    const float* gw2  = (const float*)d_in[4];
    const float* tcw  = (const float*)d_in[5];
    const float* bns  = (const float*)d_in[6];
    const float* bnb  = (const float*)d_in[7];
    const float* bnm  = (const float*)d_in[8];
    const float* bnv  = (const float*)d_in[9];
    const float* lns  = (const float*)d_in[10];
    const float* lnb  = (const float*)d_in[11];
    const float* fw   = (const float*)d_in[12];
    const float* fb   = (const float*)d_in[13];
    float* outp = (float*)d_out;

    float *bufA, *bufB, *MT1, *MT2, *part;
    cudaGetSymbolAddress((void**)&bufA, g_bufA);
    cudaGetSymbolAddress((void**)&bufB, g_bufB);
    cudaGetSymbolAddress((void**)&MT1, g_MT1);
    cudaGetSymbolAddress((void**)&MT2, g_MT2);
    cudaGetSymbolAddress((void**)&part, g_part);

    // smem floats: A slab + B (64*196) + inv/bet (128) + adjT (170) + pool (1024)
    const size_t smem1 = (size_t)(578 * 68 + 64 * 196 + 128 + 170 + 1024) * 4;  // 212,680 B
    const size_t smem2 = (size_t)(612 * 68 + 64 * 196 + 128 + 170 + 1024) * 4;  // 221,928 B
    cudaFuncSetAttribute(layer_kernel<1, false>,
                         cudaFuncAttributeMaxDynamicSharedMemorySize, (int)smem1);
    cudaFuncSetAttribute(layer_kernel<2, true>,
                         cudaFuncAttributeMaxDynamicSharedMemorySize, (int)smem2);

    prep_kernel<<<(9 * 64 + 2 * 192 * 64 + 255) / 256, 256>>>(gw0, gw1, gw2, tcw);
    adjprep_kernel<<<1, 32>>>(adj);

    dim3 g0(TDIM / TT, BATCH);     // 128 x 32
    blk0_kernel<<<g0, 512>>>(kpts, bns, bnb, bnm, bnv, bufA);

    dim3 gl(TDIM / TT2, BATCH);    // 64 x 32
    layer_kernel<1, false><<<gl, 512, smem1>>>(
        bufA, MT1, bns + 64,  bnb + 64,  bnm + 64,  bnv + 64,  bufB);
    layer_kernel<2, true><<<gl, 512, smem2>>>(
        bufB, MT2, bns + 128, bnb + 128, bnm + 128, bnv + 128, part);

    head_kernel<<<BATCH, 64>>>(lns, lnb, fw, fb, outp);
}

// round 7
// speedup vs baseline: 4.4607x; 1.1082x over previous
#include <cuda_runtime.h>

// ---------------- problem constants ----------------
#define BATCH 32
#define TDIM  2048
#define KP    17
#define HID   64
#define NPOS  (TDIM * KP)   // 34816
#define TT    16            // blk0 time tile
#define CPOS  512           // layer kernel positions per CTA
#define NZ    5

typedef unsigned long long ull;
typedef unsigned int u32;

// ---------------- device scratch ----------------
__device__ float g_bufA[(size_t)BATCH * NPOS * HID];
__device__ float g_bufB[(size_t)BATCH * NPOS * HID];
__device__ float g_M0[9 * 64];          // blk0 folded weights (fp32)
__device__ float g_MT1[64 * 192];       // layer1 B: [out_ch][k] tf32-rounded
__device__ float g_MT2[64 * 192];       // layer2 B
__device__ float2 g_adjT[KP * NZ];      // {w, bitcast(k*64)}
__device__ float2 g_adjT0[KP * NZ];     // {w, bitcast(k*3)}
__device__ float g_part[(size_t)BATCH * 68 * 64];   // pool partials [b][ctaX][c]

// ---------------- helpers ----------------
__device__ __forceinline__ ull pack2_dup(float x) {
    ull r; u32 xb = __float_as_uint(x);
    asm("mov.b64 %0, {%1, %1};" : "=l"(r) : "r"(xb));
    return r;
}
__device__ __forceinline__ void fma2(ull& c, ull a, ull b) {
    asm("fma.rn.f32x2 %0, %1, %2, %3;" : "=l"(c) : "l"(a), "l"(b), "l"(c));
}
__device__ __forceinline__ float2 unpack2(ull v) {
    u32 lo, hi;
    asm("mov.b64 {%0, %1}, %2;" : "=r"(lo), "=r"(hi) : "l"(v));
    return make_float2(__uint_as_float(lo), __uint_as_float(hi));
}
__device__ __forceinline__ u32 f2tf(float f) {
    u32 u; asm("cvt.rna.tf32.f32 %0, %1;" : "=r"(u) : "f"(f)); return u;
}
__device__ __forceinline__ void mma_tf32(float* c, const u32* a, const u32* b) {
    asm volatile(
        "mma.sync.aligned.m16n8k8.row.col.f32.tf32.tf32.f32 "
        "{%0,%1,%2,%3}, {%4,%5,%6,%7}, {%8,%9}, {%0,%1,%2,%3};"
        : "+f"(c[0]), "+f"(c[1]), "+f"(c[2]), "+f"(c[3])
        : "r"(a[0]), "r"(a[1]), "r"(a[2]), "r"(a[3]), "r"(b[0]), "r"(b[1]));
}

// ---------------- weight folding ----------------
__global__ void prep_kernel(const float* __restrict__ gw0,
                            const float* __restrict__ gw1,
                            const float* __restrict__ gw2,
                            const float* __restrict__ tcw) {
    int id = blockIdx.x * blockDim.x + threadIdx.x;
    const int n0 = 9 * 64, n1 = 192 * 64;
    if (id >= n0 + 2 * n1) return;
    int blk, cin, e; const float* gw;
    if (id < n0)           { blk = 0; cin = 3;  gw = gw0; e = id; }
    else if (id < n0 + n1) { blk = 1; cin = 64; gw = gw1; e = id - n0; }
    else                   { blk = 2; cin = 64; gw = gw2; e = id - n0 - n1; }
    int km = e / 64, o = e % 64;
    int j = km / cin, c = km % cin;
    const float* tw = tcw + (size_t)blk * HID * HID * 3;
    float s = 0.f;
    for (int h = 0; h < HID; ++h)
        s = fmaf(gw[c * HID + h], tw[(o * HID + h) * 3 + j], s);
    if (blk == 0) g_M0[km * 64 + o] = s;
    else {
        float* MT = (blk == 1) ? g_MT1 : g_MT2;
        MT[o * 192 + km] = __uint_as_float(f2tf(s));
    }
}

__global__ void adjprep_kernel(const float* __restrict__ adj) {
    int v = threadIdx.x;
    if (v >= KP) return;
    int cnt = 0;
    for (int k = 0; k < KP; ++k) {
        float w = adj[k * KP + v];
        if (w != 0.0f && cnt < NZ) {
            g_adjT [v * NZ + cnt] = make_float2(w, __int_as_float(k * 64));
            g_adjT0[v * NZ + cnt] = make_float2(w, __int_as_float(k * 3));
            ++cnt;
        }
    }
    for (; cnt < NZ; ++cnt) {
        g_adjT [v * NZ + cnt] = make_float2(0.0f, __int_as_float(0));
        g_adjT0[v * NZ + cnt] = make_float2(0.0f, __int_as_float(0));
    }
}

// ---------------- block 0 (fp32 FFMA2 path, CIN=3) ----------------
__global__ void __launch_bounds__(512) blk0_kernel(
    const float* __restrict__ kpts,
    const float* __restrict__ bns, const float* __restrict__ bnb,
    const float* __restrict__ bnm, const float* __restrict__ bnv,
    float* __restrict__ out)
{
    constexpr int PR = (TT + 2) * KP;   // 306
    __shared__ float  sM0[9 * 64];
    __shared__ ull    sZ[PR * 4];
    __shared__ float  sBN[128];
    __shared__ float2 sT[KP * NZ];

    const int tid = threadIdx.x;
    const int b   = blockIdx.y;
    const int t0  = blockIdx.x * TT;

    for (int i = tid; i < 9 * 64; i += 512) sM0[i] = g_M0[i];
    if (tid < KP * NZ) sT[tid] = g_adjT0[tid];
    if (tid < 64) {
        float inv = __ldg(bns + tid) * rsqrtf(__ldg(bnv + tid) + 1e-5f);
        sBN[tid] = inv;
        sBN[64 + tid] = __ldg(bnb + tid) - __ldg(bnm + tid) * inv;
    }
    __syncthreads();

    for (int idx = tid; idx < PR * 3; idx += 512) {
        int ph = idx / 3, c = idx - ph * 3;
        int h = ph / KP, kk = ph - h * KP;
        int t = t0 - 1 + h;
        float v = 0.f;
        if ((unsigned)t < (unsigned)TDIM) {
            const float* xr = kpts + (size_t)(b * TDIM + t) * (KP * 3);
#pragma unroll
            for (int e = 0; e < NZ; ++e) {
                float2 wt = sT[kk * NZ + e];
                v = fmaf(wt.x, xr[__float_as_int(wt.y) + c], v);
            }
        }
        sZ[ph * 4 + c] = pack2_dup(v);
    }
    __syncthreads();

    const int cg = tid & 7, rt = tid >> 3;
    const int o1 = cg * 4, o2 = 32 + o1;
    const size_t gb = (size_t)(b * TDIM + t0) * KP;
    const float4 invA = *(const float4*)(sBN + o1);
    const float4 invB = *(const float4*)(sBN + o2);
    const float4 betA = *(const float4*)(sBN + 64 + o1);
    const float4 betB = *(const float4*)(sBN + 64 + o2);

    for (int it = 0; it < 2; ++it) {
        bool act = (it == 0) || (tid < 32);
        if (!act) continue;
        const int prow = (it ? 64 + rt : rt);

        ull acc[4][4] = {};
#pragma unroll
        for (int j = 0; j < 3; ++j) {
            const ull* zb = sZ + (prow + j * KP) * 4;
#pragma unroll
            for (int c = 0; c < 3; ++c) {
                const float* mk = sM0 + (j * 3 + c) * 64;
                ulonglong2 m1 = *(const ulonglong2*)(mk + o1);
                ulonglong2 m2 = *(const ulonglong2*)(mk + o2);
#pragma unroll
                for (int i = 0; i < 4; ++i) {
                    ull av = zb[i * 68 * 4 + c];
                    fma2(acc[i][0], av, m1.x); fma2(acc[i][1], av, m1.y);
                    fma2(acc[i][2], av, m2.x); fma2(acc[i][3], av, m2.y);
                }
            }
        }
#pragma unroll
        for (int i = 0; i < 4; ++i) {
            float2 q0 = unpack2(acc[i][0]), q1 = unpack2(acc[i][1]);
            float2 q2 = unpack2(acc[i][2]), q3 = unpack2(acc[i][3]);
            size_t rowo = (gb + prow + 68 * i) * 64;
            float4 v1, v2;
            v1.x = fmaxf(fmaf(q0.x, invA.x, betA.x), 0.f);
            v1.y = fmaxf(fmaf(q0.y, invA.y, betA.y), 0.f);
            v1.z = fmaxf(fmaf(q1.x, invA.z, betA.z), 0.f);
            v1.w = fmaxf(fmaf(q1.y, invA.w, betA.w), 0.f);
            v2.x = fmaxf(fmaf(q2.x, invB.x, betB.x), 0.f);
            v2.y = fmaxf(fmaf(q2.y, invB.y, betB.y), 0.f);
            v2.z = fmaxf(fmaf(q3.x, invB.z, betB.z), 0.f);
            v2.w = fmaxf(fmaf(q3.y, invB.w, betB.w), 0.f);
            *(float4*)(out + rowo + o1) = v1;
            *(float4*)(out + rowo + o2) = v2;
        }
    }
}

// ---------------- layers 1 & 2: flat-position tiling, tf32 mma.sync ----------------
// CTA covers CPOS=512 flat positions; warp w owns rows [w*32, w*32+32) = 2 m16 tiles.
// A slab rows: [cta_start - NSH, cta_start + 512 + NSH), adj-premixed + tf32.
template <int DIL, bool POOL>
__global__ void __launch_bounds__(512) layer_kernel(
    const float* __restrict__ Y,            // input (also residual), compact [NPOS][64]
    const float* __restrict__ MT,           // [64][192] tf32 weights
    const float* __restrict__ bns, const float* __restrict__ bnb,
    const float* __restrict__ bnm, const float* __restrict__ bnv,
    float* __restrict__ outp)
{
    constexpr int NSH = KP * DIL;                // tap row shift
    constexpr int RA  = CPOS + 2 * NSH;          // 546 / 580
    constexpr int ZS  = 68;
    constexpr int OFF_B   = RA * ZS;
    constexpr int OFF_INV = OFF_B + 64 * 196;
    constexpr int OFF_BET = OFF_INV + 64;
    constexpr int OFF_T   = OFF_BET + 64;
    constexpr int OFF_PL  = OFF_T + 170;

    extern __shared__ float sm[];
    u32*    sZu  = (u32*)sm;
    u32*    sBu  = (u32*)(sm + OFF_B);
    float*  sInv = sm + OFF_INV;
    float*  sBet = sm + OFF_BET;
    float2* sT   = (float2*)(sm + OFF_T);
    float*  sPl  = sm + OFF_PL;

    const int tid = threadIdx.x;
    const int wid = tid >> 5, lid = tid & 31;
    const int g = lid >> 2, tig = lid & 3;
    const int b = blockIdx.y;
    const int p0 = blockIdx.x * CPOS;            // first output position
    const float* Yb = Y + (size_t)b * NPOS * 64;

    if (tid < KP * NZ) sT[tid] = g_adjT[tid];
    if (tid < 64) {
        float inv = __ldg(bns + tid) * rsqrtf(__ldg(bnv + tid) + 1e-5f);
        sInv[tid] = inv;
        sBet[tid] = __ldg(bnb + tid) - __ldg(bnm + tid) * inv;
    }
    for (int idx = tid; idx < 64 * 48; idx += 512) {
        int r = idx / 48, c4 = idx - r * 48;
        *(uint4*)(sBu + r * 196 + c4 * 4) = *(const uint4*)(MT + r * 192 + c4 * 4);
    }
    __syncthreads();

    // A slab staging: slab row zr -> global position p0 - NSH + zr
    for (int idx = tid; idx < RA * 16; idx += 512) {
        int zr = idx >> 4, c4 = idx & 15;
        int p = p0 - NSH + zr;
        uint4 o = make_uint4(0, 0, 0, 0);
        if ((unsigned)p < (unsigned)NPOS) {
            int t = p / KP, kk = p - t * KP;
            const float* xr = Yb + (size_t)t * (KP * 64) + c4 * 4;
            float4 v = make_float4(0.f, 0.f, 0.f, 0.f);
#pragma unroll
            for (int e = 0; e < NZ; ++e) {
                float2 wt = sT[kk * NZ + e];
                const float4 xa = *(const float4*)(xr + __float_as_int(wt.y));
                v.x = fmaf(wt.x, xa.x, v.x);
                v.y = fmaf(wt.x, xa.y, v.y);
                v.z = fmaf(wt.x, xa.z, v.z);
                v.w = fmaf(wt.x, xa.w, v.w);
            }
            o.x = f2tf(v.x); o.y = f2tf(v.y); o.z = f2tf(v.z); o.w = f2tf(v.w);
        }
        *(uint4*)(sZu + zr * ZS + c4 * 4) = o;
    }
    __syncthreads();

    // GEMM: warp owns local rows [wid*32, wid*32+32) = 2 m16 tiles, B regs shared
    float c[2][8][4];
#pragma unroll
    for (int ti = 0; ti < 2; ++ti)
#pragma unroll
        for (int i = 0; i < 8; ++i)
#pragma unroll
            for (int n = 0; n < 4; ++n) c[ti][i][n] = 0.f;

    const int rbase = wid * 32 + NSH + g;   // slab row for tap 0... tap j adds (j-1)*... see below
#pragma unroll
    for (int tap = 0; tap < 3; ++tap) {
        // output local row r -> slab row r + tap*NSH (slab origin is -NSH)
        const u32* za = sZu + (wid * 32 + tap * NSH + g) * ZS + tig;
#pragma unroll
        for (int k8 = 0; k8 < 8; ++k8) {
            const u32* zp = za + k8 * 8;
            u32 a0[4], a1[4];
            a0[0] = zp[0];            a0[1] = zp[8 * ZS];
            a0[2] = zp[4];            a0[3] = zp[8 * ZS + 4];
            a1[0] = zp[16 * ZS];      a1[1] = zp[24 * ZS];
            a1[2] = zp[16 * ZS + 4];  a1[3] = zp[24 * ZS + 4];
            const int kcol = tap * 64 + k8 * 8 + tig;
            u32 bf[8][2];
#pragma unroll
            for (int i = 0; i < 8; ++i) {
                const u32* bp = sBu + (8 * i + g) * 196 + kcol;
                bf[i][0] = bp[0];
                bf[i][1] = bp[4];
            }
#pragma unroll
            for (int i = 0; i < 8; ++i) {
                mma_tf32(c[0][i], a0, bf[i]);
                mma_tf32(c[1][i], a1, bf[i]);
            }
        }
    }
    (void)rbase;

    // epilogue
    float ps[16];
    if (POOL) {
#pragma unroll
        for (int i = 0; i < 16; ++i) ps[i] = 0.f;
    }
    const size_t gbase = (size_t)b * NPOS + p0;
#pragma unroll
    for (int ti = 0; ti < 2; ++ti) {
        const int row0 = wid * 32 + ti * 16;
        const size_t grow = (gbase + row0 + g) * 64;
        const float* rp = Y + grow;
        float* op = POOL ? nullptr : (outp + grow);
#pragma unroll
        for (int i = 0; i < 8; ++i) {
            const int ch = 8 * i + 2 * tig;
            const float2 inv = *(const float2*)(sInv + ch);
            const float2 bet = *(const float2*)(sBet + ch);
            const float2 r0v = *(const float2*)(rp + ch);
            const float2 r1v = *(const float2*)(rp + 8 * 64 + ch);
            float v0 = fmaxf(fmaf(c[ti][i][0], inv.x, bet.x), 0.f) + r0v.x;
            float v1 = fmaxf(fmaf(c[ti][i][1], inv.y, bet.y), 0.f) + r0v.y;
            float v2 = fmaxf(fmaf(c[ti][i][2], inv.x, bet.x), 0.f) + r1v.x;
            float v3 = fmaxf(fmaf(c[ti][i][3], inv.y, bet.y), 0.f) + r1v.y;
            if (POOL) {
                ps[2 * i]     += v0 + v2;
                ps[2 * i + 1] += v1 + v3;
            } else {
                *(float2*)(op + ch)          = make_float2(v0, v1);
                *(float2*)(op + 8 * 64 + ch) = make_float2(v2, v3);
            }
        }
    }

    if (POOL) {
#pragma unroll
        for (int i = 0; i < 16; ++i) {
            ps[i] += __shfl_xor_sync(0xFFFFFFFF, ps[i], 4);
            ps[i] += __shfl_xor_sync(0xFFFFFFFF, ps[i], 8);
            ps[i] += __shfl_xor_sync(0xFFFFFFFF, ps[i], 16);
        }
        if (g == 0) {
#pragma unroll
            for (int i = 0; i < 8; ++i) {
                sPl[wid * 64 + 8 * i + 2 * tig]     = ps[2 * i];
                sPl[wid * 64 + 8 * i + 2 * tig + 1] = ps[2 * i + 1];
            }
        }
        __syncthreads();
        if (tid < 64) {
            float s = 0.f;
            for (int w = 0; w < 16; ++w)
                s += sPl[w * 64 + tid];
            outp[((size_t)b * 68 + blockIdx.x) * 64 + tid] = s;
        }
    }
}

// ---------------- head: pool finish + LN + FC ----------------
__global__ void head_kernel(const float* __restrict__ lns, const float* __restrict__ lnb,
                            const float* __restrict__ fw,  const float* __restrict__ fb,
                            float* __restrict__ outp) {
    __shared__ float f[64];
    __shared__ float mu_s, rv_s;
    const int b = blockIdx.x, tid = threadIdx.x;
    float s = 0.f;
    for (int i = 0; i < 68; ++i)
        s += g_part[((size_t)b * 68 + i) * 64 + tid];
    float v = s * (1.0f / (float)NPOS);
    f[tid] = v;
    __syncthreads();
    if (tid == 0) {
        float m = 0.f;
        for (int i = 0; i < 64; ++i) m += f[i];
        m *= (1.0f / 64.0f);
        float va = 0.f;
        for (int i = 0; i < 64; ++i) { float d = f[i] - m; va = fmaf(d, d, va); }
        va *= (1.0f / 64.0f);
        mu_s = m; rv_s = rsqrtf(va + 1e-5f);
    }
    __syncthreads();
    float nf = (v - mu_s) * rv_s * lns[tid] + lnb[tid];
    __syncthreads();
    f[tid] = nf;
    __syncthreads();
    if (tid < 10) {
        float o = fb[tid];
        for (int c = 0; c < 64; ++c)
            o = fmaf(f[c], fw[c * 10 + tid], o);
        outp[b * 10 + tid] = o;
    }
}

// ---------------- launch ----------------
extern "C" void kernel_launch(void* const* d_in, const int* in_sizes, int n_in,
                              void* d_out, int out_size) {
    const float* kpts = (const float*)d_in[0];
    const float* adj  = (const float*)d_in[1];
    const float* gw0  = (const float*)d_in[2];
    const float* gw1  = (const float*)d_in[3];
    const float* gw2  = (const float*)d_in[4];
    const float* tcw  = (const float*)d_in[5];
    const float* bns  = (const float*)d_in[6];
    const float* bnb  = (const float*)d_in[7];
    const float* bnm  = (const float*)d_in[8];
    const float* bnv  = (const float*)d_in[9];
    const float* lns  = (const float*)d_in[10];
    const float* lnb  = (const float*)d_in[11];
    const float* fw   = (const float*)d_in[12];
    const float* fb   = (const float*)d_in[13];
    float* outp = (float*)d_out;

    float *bufA, *bufB, *MT1, *MT2, *part;
    cudaGetSymbolAddress((void**)&bufA, g_bufA);
    cudaGetSymbolAddress((void**)&bufB, g_bufB);
    cudaGetSymbolAddress((void**)&MT1, g_MT1);
    cudaGetSymbolAddress((void**)&MT2, g_MT2);
    cudaGetSymbolAddress((void**)&part, g_part);

    // smem floats: A slab + B(64*196) + inv/bet(128) + adjT(170) + pool(1024)
    const size_t smem1 = (size_t)(546 * 68 + 64 * 196 + 128 + 170 + 1024) * 4;  // 204,008 B
    const size_t smem2 = (size_t)(580 * 68 + 64 * 196 + 128 + 170 + 1024) * 4;  // 213,256 B
    cudaFuncSetAttribute(layer_kernel<1, false>,
                         cudaFuncAttributeMaxDynamicSharedMemorySize, (int)smem1);
    cudaFuncSetAttribute(layer_kernel<2, true>,
                         cudaFuncAttributeMaxDynamicSharedMemorySize, (int)smem2);

    prep_kernel<<<(9 * 64 + 2 * 192 * 64 + 255) / 256, 256>>>(gw0, gw1, gw2, tcw);
    adjprep_kernel<<<1, 32>>>(adj);

    dim3 g0(TDIM / TT, BATCH);     // 128 x 32
    blk0_kernel<<<g0, 512>>>(kpts, bns, bnb, bnm, bnv, bufA);

    dim3 gl(NPOS / CPOS, BATCH);   // 68 x 32
    layer_kernel<1, false><<<gl, 512, smem1>>>(
        bufA, MT1, bns + 64,  bnb + 64,  bnm + 64,  bnv + 64,  bufB);
    layer_kernel<2, true><<<gl, 512, smem2>>>(
        bufB, MT2, bns + 128, bnb + 128, bnm + 128, bnv + 128, part);

    head_kernel<<<BATCH, 64>>>(lns, lnb, fw, fb, outp);
}

// round 10
// speedup vs baseline: 4.5906x; 1.0291x over previous
#include <cuda_runtime.h>

// ---------------- problem constants ----------------
#define BATCH 32
#define TDIM  2048
#define KP    17
#define HID   64
#define NPOS  (TDIM * KP)   // 34816
#define TT    16            // blk0 time tile
#define CPOS  480           // output positions per layer CTA
#define GR    512           // GEMM rows per CTA (CPOS + 2*16 halo)
#define NCTA  73            // ceil(NPOS / CPOS)
#define NZ    5

typedef unsigned long long ull;
typedef unsigned int u32;

// ---------------- device scratch ----------------
__device__ float g_bufA[(size_t)BATCH * NPOS * HID];
__device__ float g_bufB[(size_t)BATCH * NPOS * HID];
__device__ float g_M0[9 * 64];            // blk0 folded weights (fp32)
__device__ float g_MTf1[24 * 8 * 64];     // layer1 B, fragment-major tf32
__device__ float g_MTf2[24 * 8 * 64];     // layer2 B
__device__ float2 g_adjD[KP * NZ];        // {w, bitcast((k_e - v)*68)} row-delta gathers
__device__ float2 g_adjT0[KP * NZ];       // {w, bitcast(k*3)} for blk0
__device__ float g_part[(size_t)BATCH * 80 * 64];   // pool partials

// ---------------- helpers ----------------
__device__ __forceinline__ ull pack2_dup(float x) {
    ull r; u32 xb = __float_as_uint(x);
    asm("mov.b64 %0, {%1, %1};" : "=l"(r) : "r"(xb));
    return r;
}
__device__ __forceinline__ void fma2(ull& c, ull a, ull b) {
    asm("fma.rn.f32x2 %0, %1, %2, %3;" : "=l"(c) : "l"(a), "l"(b), "l"(c));
}
__device__ __forceinline__ float2 unpack2(ull v) {
    u32 lo, hi;
    asm("mov.b64 {%0, %1}, %2;" : "=r"(lo), "=r"(hi) : "l"(v));
    return make_float2(__uint_as_float(lo), __uint_as_float(hi));
}
__device__ __forceinline__ u32 f2tf(float f) {
    u32 u; asm("cvt.rna.tf32.f32 %0, %1;" : "=r"(u) : "f"(f)); return u;
}
__device__ __forceinline__ void mma_tf32(float* c, const u32* a, const u32* b) {
    asm volatile(
        "mma.sync.aligned.m16n8k8.row.col.f32.tf32.tf32.f32 "
        "{%0,%1,%2,%3}, {%4,%5,%6,%7}, {%8,%9}, {%0,%1,%2,%3};"
        : "+f"(c[0]), "+f"(c[1]), "+f"(c[2]), "+f"(c[3])
        : "r"(a[0]), "r"(a[1]), "r"(a[2]), "r"(a[3]), "r"(b[0]), "r"(b[1]));
}

// ---------------- weight folding (fragment-major for layers 1/2) ----------------
__global__ void prep_kernel(const float* __restrict__ gw0,
                            const float* __restrict__ gw1,
                            const float* __restrict__ gw2,
                            const float* __restrict__ tcw) {
    int id = blockIdx.x * blockDim.x + threadIdx.x;
    const int n0 = 9 * 64, n1 = 192 * 64;
    if (id >= n0 + 2 * n1) return;
    int blk, cin, e; const float* gw;
    if (id < n0)           { blk = 0; cin = 3;  gw = gw0; e = id; }
    else if (id < n0 + n1) { blk = 1; cin = 64; gw = gw1; e = id - n0; }
    else                   { blk = 2; cin = 64; gw = gw2; e = id - n0 - n1; }
    int km = e / 64, o = e % 64;
    int j = km / cin, c = km % cin;
    const float* tw = tcw + (size_t)blk * HID * HID * 3;
    float s = 0.f;
    for (int h = 0; h < HID; ++h)
        s = fmaf(gw[c * HID + h], tw[(o * HID + h) * 3 + j], s);
    if (blk == 0) { g_M0[km * 64 + o] = s; return; }
    // fragment-major slot: thread lane (g,tig) holds B[km=s8*8+tig+4h][o=8i+g]
    int s8 = km >> 3, r8 = km & 7;
    int tig = r8 & 3, h = r8 >> 2;
    int i = o >> 3, g = o & 7;
    int slot = ((s8 * 8 + i) * 32 + (g * 4 + tig)) * 2 + h;
    float* MT = (blk == 1) ? g_MTf1 : g_MTf2;
    MT[slot] = __uint_as_float(f2tf(s));
}

__global__ void adjprep_kernel(const float* __restrict__ adj) {
    int v = threadIdx.x;
    if (v >= KP) return;
    int cnt = 0;
    for (int k = 0; k < KP; ++k) {
        float w = adj[k * KP + v];
        if (w != 0.0f && cnt < NZ) {
            g_adjD [v * NZ + cnt] = make_float2(w, __int_as_float((k - v) * 68));
            g_adjT0[v * NZ + cnt] = make_float2(w, __int_as_float(k * 3));
            ++cnt;
        }
    }
    for (; cnt < NZ; ++cnt) {
        g_adjD [v * NZ + cnt] = make_float2(0.0f, __int_as_float(0));
        g_adjT0[v * NZ + cnt] = make_float2(0.0f, __int_as_float(0));
    }
}

// ---------------- block 0 (fp32 FFMA2 path, CIN=3) ----------------
__global__ void __launch_bounds__(512) blk0_kernel(
    const float* __restrict__ kpts,
    const float* __restrict__ bns, const float* __restrict__ bnb,
    const float* __restrict__ bnm, const float* __restrict__ bnv,
    float* __restrict__ out)
{
    constexpr int PR = (TT + 2) * KP;   // 306
    __shared__ float  sM0[9 * 64];
    __shared__ ull    sZ[PR * 4];
    __shared__ float  sBN[128];
    __shared__ float2 sT[KP * NZ];

    const int tid = threadIdx.x;
    const int b   = blockIdx.y;
    const int t0  = blockIdx.x * TT;

    for (int i = tid; i < 9 * 64; i += 512) sM0[i] = g_M0[i];
    if (tid < KP * NZ) sT[tid] = g_adjT0[tid];
    if (tid < 64) {
        float inv = __ldg(bns + tid) * rsqrtf(__ldg(bnv + tid) + 1e-5f);
        sBN[tid] = inv;
        sBN[64 + tid] = __ldg(bnb + tid) - __ldg(bnm + tid) * inv;
    }
    __syncthreads();

    for (int idx = tid; idx < PR * 3; idx += 512) {
        int ph = idx / 3, c = idx - ph * 3;
        int h = ph / KP, kk = ph - h * KP;
        int t = t0 - 1 + h;
        float v = 0.f;
        if ((unsigned)t < (unsigned)TDIM) {
            const float* xr = kpts + (size_t)(b * TDIM + t) * (KP * 3);
#pragma unroll
            for (int e = 0; e < NZ; ++e) {
                float2 wt = sT[kk * NZ + e];
                v = fmaf(wt.x, xr[__float_as_int(wt.y) + c], v);
            }
        }
        sZ[ph * 4 + c] = pack2_dup(v);
    }
    __syncthreads();

    const int cg = tid & 7, rt = tid >> 3;
    const int o1 = cg * 4, o2 = 32 + o1;
    const size_t gb = (size_t)(b * TDIM + t0) * KP;
    const float4 invA = *(const float4*)(sBN + o1);
    const float4 invB = *(const float4*)(sBN + o2);
    const float4 betA = *(const float4*)(sBN + 64 + o1);
    const float4 betB = *(const float4*)(sBN + 64 + o2);

    for (int it = 0; it < 2; ++it) {
        bool act = (it == 0) || (tid < 32);
        if (!act) continue;
        const int prow = (it ? 64 + rt : rt);

        ull acc[4][4] = {};
#pragma unroll
        for (int j = 0; j < 3; ++j) {
            const ull* zb = sZ + (prow + j * KP) * 4;
#pragma unroll
            for (int c = 0; c < 3; ++c) {
                const float* mk = sM0 + (j * 3 + c) * 64;
                ulonglong2 m1 = *(const ulonglong2*)(mk + o1);
                ulonglong2 m2 = *(const ulonglong2*)(mk + o2);
#pragma unroll
                for (int i = 0; i < 4; ++i) {
                    ull av = zb[i * 68 * 4 + c];
                    fma2(acc[i][0], av, m1.x); fma2(acc[i][1], av, m1.y);
                    fma2(acc[i][2], av, m2.x); fma2(acc[i][3], av, m2.y);
                }
            }
        }
#pragma unroll
        for (int i = 0; i < 4; ++i) {
            float2 q0 = unpack2(acc[i][0]), q1 = unpack2(acc[i][1]);
            float2 q2 = unpack2(acc[i][2]), q3 = unpack2(acc[i][3]);
            size_t rowo = (gb + prow + 68 * i) * 64;
            float4 v1, v2;
            v1.x = fmaxf(fmaf(q0.x, invA.x, betA.x), 0.f);
            v1.y = fmaxf(fmaf(q0.y, invA.y, betA.y), 0.f);
            v1.z = fmaxf(fmaf(q1.x, invA.z, betA.z), 0.f);
            v1.w = fmaxf(fmaf(q1.y, invA.w, betA.w), 0.f);
            v2.x = fmaxf(fmaf(q2.x, invB.x, betB.x), 0.f);
            v2.y = fmaxf(fmaf(q2.y, invB.y, betB.y), 0.f);
            v2.z = fmaxf(fmaf(q3.x, invB.z, betB.z), 0.f);
            v2.w = fmaxf(fmaf(q3.y, invB.w, betB.w), 0.f);
            *(float4*)(out + rowo + o1) = v1;
            *(float4*)(out + rowo + o2) = v2;
        }
    }
}

// ---------------- layers 1 & 2: raw-GEMM + epilogue adj-mix ----------------
template <int DIL, bool POOL>
__global__ void __launch_bounds__(512) layer_kernel(
    const float* __restrict__ Y,
    const float* __restrict__ MTf,
    const float* __restrict__ bns, const float* __restrict__ bnb,
    const float* __restrict__ bnm, const float* __restrict__ bnv,
    float* __restrict__ outp)
{
    constexpr int NSH = KP * DIL;
    constexpr int RA  = GR + 2 * NSH;       // 546 / 580
    constexpr int ZS  = 68;
    constexpr int OFF_B   = RA * ZS;
    constexpr int OFF_INV = OFF_B + 12288;
    constexpr int OFF_BET = OFF_INV + 64;
    constexpr int OFF_T   = OFF_BET + 64;
    constexpr int OFF_PL  = OFF_T + 176;     // 16B-aligned (adjT uses 170, pad to 176)

    extern __shared__ float sm[];
    u32*    sZu  = (u32*)sm;                 // raw A slab (k-permuted tf32)
    u32*    sBf  = (u32*)(sm + OFF_B);       // B fragment-major
    float*  sInv = sm + OFF_INV;
    float*  sBet = sm + OFF_BET;
    float2* sT   = (float2*)(sm + OFF_T);
    float*  sPl  = sm + OFF_PL;
    float*  sD   = sm;                       // D buffer aliases slab (post-GEMM)

    const int tid = threadIdx.x;
    const int wid = tid >> 5, lid = tid & 31;
    const int g = lid >> 2, tig = lid & 3;
    const int b = blockIdx.y;
    const int p0 = blockIdx.x * CPOS;
    const int pbase = p0 - 16 - NSH;         // position of slab row 0
    const float* Yb = Y + (size_t)b * NPOS * 64;

    if (tid < KP * NZ) sT[tid] = g_adjD[tid];
    if (tid < 64) {
        float inv = __ldg(bns + tid) * rsqrtf(__ldg(bnv + tid) + 1e-5f);
        sInv[tid] = inv;
        sBet[tid] = __ldg(bnb + tid) - __ldg(bnm + tid) * inv;
    }
    // B: linear copy (prep wrote fragment-major)
    for (int i = tid; i < 3072; i += 512)
        *(uint4*)(sBf + i * 4) = *(const uint4*)(MTf + i * 4);

    // raw A staging: 1x coalesced, channel-permuted within 8-groups, tf32
    for (int idx = tid; idx < RA * 8; idx += 512) {
        int zr = idx >> 3, g8 = idx & 7;
        int p = pbase + zr;
        uint4 d0 = make_uint4(0, 0, 0, 0), d1 = make_uint4(0, 0, 0, 0);
        if ((unsigned)p < (unsigned)NPOS) {
            const float4 q0 = *(const float4*)(Yb + (size_t)p * 64 + g8 * 8);
            const float4 q1 = *(const float4*)(Yb + (size_t)p * 64 + g8 * 8 + 4);
            d0.x = f2tf(q0.x); d0.y = f2tf(q1.x); d0.z = f2tf(q0.y); d0.w = f2tf(q1.y);
            d1.x = f2tf(q0.z); d1.y = f2tf(q1.z); d1.z = f2tf(q0.w); d1.w = f2tf(q1.w);
        }
        u32* zp = sZu + zr * ZS + g8 * 8;
        *(uint4*)zp       = d0;
        *(uint4*)(zp + 4) = d1;
    }
    __syncthreads();

    // ---- GEMM: warp owns GEMM rows [wid*32, wid*32+32) = 2 m16 tiles ----
    float c[2][8][4];
#pragma unroll
    for (int ti = 0; ti < 2; ++ti)
#pragma unroll
        for (int i = 0; i < 8; ++i)
#pragma unroll
            for (int n = 0; n < 4; ++n) c[ti][i][n] = 0.f;

#pragma unroll
    for (int tap = 0; tap < 3; ++tap) {
        const u32* za = sZu + (wid * 32 + tap * NSH + g) * ZS + 2 * tig;
#pragma unroll
        for (int k8 = 0; k8 < 8; ++k8) {
            const u32* zp = za + k8 * 8;
            u32 a0[4], a1[4];
            { uint2 v = *(const uint2*)zp;                a0[0] = v.x; a0[2] = v.y; }
            { uint2 v = *(const uint2*)(zp +  8 * ZS);    a0[1] = v.x; a0[3] = v.y; }
            { uint2 v = *(const uint2*)(zp + 16 * ZS);    a1[0] = v.x; a1[2] = v.y; }
            { uint2 v = *(const uint2*)(zp + 24 * ZS);    a1[1] = v.x; a1[3] = v.y; }
            const u32* bb = sBf + ((tap * 8 + k8) * 8) * 64 + lid * 2;
#pragma unroll
            for (int i = 0; i < 8; ++i) {
                uint2 bv = *(const uint2*)(bb + i * 64);
                u32 bf[2] = {bv.x, bv.y};
                mma_tf32(c[0][i], a0, bf);
                mma_tf32(c[1][i], a1, bf);
            }
        }
    }
    __syncthreads();   // all slab reads done; reuse as D buffer

    // ---- D store: rows stride 68, logical channels ----
#pragma unroll
    for (int ti = 0; ti < 2; ++ti) {
        const int r0 = wid * 32 + ti * 16 + g;
#pragma unroll
        for (int i = 0; i < 8; ++i) {
            *(float2*)(sD + r0 * ZS + 8 * i + 2 * tig)       = make_float2(c[ti][i][0], c[ti][i][1]);
            *(float2*)(sD + (r0 + 8) * ZS + 8 * i + 2 * tig) = make_float2(c[ti][i][2], c[ti][i][3]);
        }
    }
    __syncthreads();

    // ---- epilogue: adj-mix from D + BN + ReLU + residual (+ pool) ----
    const int c4 = tid & 15;                 // channel quad, constant per thread
    const float4 inv4 = *(const float4*)(sInv + c4 * 4);
    const float4 bet4 = *(const float4*)(sBet + c4 * 4);
    float ps[4] = {0.f, 0.f, 0.f, 0.f};
    float* ob = outp ? (outp + (size_t)b * NPOS * 64) : nullptr;

#pragma unroll 3
    for (int it = 0; it < 15; ++it) {
        const int r = (it * 512 + tid) >> 4;        // output row 0..479
        const int p = p0 + r;
        if (p < NPOS) {
            const int k = p - (p / KP) * KP;
            const float* drow = sD + (r + 16) * ZS + c4 * 4;
            float4 s = make_float4(0.f, 0.f, 0.f, 0.f);
#pragma unroll
            for (int e = 0; e < NZ; ++e) {
                float2 wt = sT[k * NZ + e];
                const float4 dv = *(const float4*)(drow + __float_as_int(wt.y));
                s.x = fmaf(wt.x, dv.x, s.x);
                s.y = fmaf(wt.x, dv.y, s.y);
                s.z = fmaf(wt.x, dv.z, s.z);
                s.w = fmaf(wt.x, dv.w, s.w);
            }
            const float4 rs = *(const float4*)(Yb + (size_t)p * 64 + c4 * 4);
            float4 v;
            v.x = fmaxf(fmaf(s.x, inv4.x, bet4.x), 0.f) + rs.x;
            v.y = fmaxf(fmaf(s.y, inv4.y, bet4.y), 0.f) + rs.y;
            v.z = fmaxf(fmaf(s.z, inv4.z, bet4.z), 0.f) + rs.z;
            v.w = fmaxf(fmaf(s.w, inv4.w, bet4.w), 0.f) + rs.w;
            if (POOL) {
                ps[0] += v.x; ps[1] += v.y; ps[2] += v.z; ps[3] += v.w;
            } else {
                *(float4*)(ob + (size_t)p * 64 + c4 * 4) = v;
            }
        }
    }

    if (POOL) {
        // lanes l and l+16 share c4 within a warp
#pragma unroll
        for (int j = 0; j < 4; ++j)
            ps[j] += __shfl_xor_sync(0xFFFFFFFF, ps[j], 16);
        if (lid < 16) {
            *(float4*)(sPl + wid * 64 + lid * 4) = make_float4(ps[0], ps[1], ps[2], ps[3]);
        }
        __syncthreads();
        if (tid < 64) {
            float s = 0.f;
            for (int w = 0; w < 16; ++w)
                s += sPl[w * 64 + tid];
            g_part[((size_t)b * 80 + blockIdx.x) * 64 + tid] = s;
        }
    }
}

// ---------------- head: pool finish + LN + FC ----------------
__global__ void head_kernel(const float* __restrict__ lns, const float* __restrict__ lnb,
                            const float* __restrict__ fw,  const float* __restrict__ fb,
                            float* __restrict__ outp) {
    __shared__ float f[64];
    __shared__ float mu_s, rv_s;
    const int b = blockIdx.x, tid = threadIdx.x;
    float s = 0.f;
    for (int i = 0; i < NCTA; ++i)
        s += g_part[((size_t)b * 80 + i) * 64 + tid];
    float v = s * (1.0f / (float)NPOS);
    f[tid] = v;
    __syncthreads();
    if (tid == 0) {
        float m = 0.f;
        for (int i = 0; i < 64; ++i) m += f[i];
        m *= (1.0f / 64.0f);
        float va = 0.f;
        for (int i = 0; i < 64; ++i) { float d = f[i] - m; va = fmaf(d, d, va); }
        va *= (1.0f / 64.0f);
        mu_s = m; rv_s = rsqrtf(va + 1e-5f);
    }
    __syncthreads();
    float nf = (v - mu_s) * rv_s * lns[tid] + lnb[tid];
    __syncthreads();
    f[tid] = nf;
    __syncthreads();
    if (tid < 10) {
        float o = fb[tid];
        for (int c = 0; c < 64; ++c)
            o = fmaf(f[c], fw[c * 10 + tid], o);
        outp[b * 10 + tid] = o;
    }
}

// ---------------- launch ----------------
extern "C" void kernel_launch(void* const* d_in, const int* in_sizes, int n_in,
                              void* d_out, int out_size) {
    const float* kpts = (const float*)d_in[0];
    const float* adj  = (const float*)d_in[1];
    const float* gw0  = (const float*)d_in[2];
    const float* gw1  = (const float*)d_in[3];
    const float* gw2  = (const float*)d_in[4];
    const float* tcw  = (const float*)d_in[5];
    const float* bns  = (const float*)d_in[6];
    const float* bnb  = (const float*)d_in[7];
    const float* bnm  = (const float*)d_in[8];
    const float* bnv  = (const float*)d_in[9];
    const float* lns  = (const float*)d_in[10];
    const float* lnb  = (const float*)d_in[11];
    const float* fw   = (const float*)d_in[12];
    const float* fb   = (const float*)d_in[13];
    float* outp = (float*)d_out;

    float *bufA, *bufB, *MT1, *MT2;
    cudaGetSymbolAddress((void**)&bufA, g_bufA);
    cudaGetSymbolAddress((void**)&bufB, g_bufB);
    cudaGetSymbolAddress((void**)&MT1, g_MTf1);
    cudaGetSymbolAddress((void**)&MT2, g_MTf2);

    // smem floats: slab RA*68 + B 12288 + inv/bet 128 + adjD pad 176 + pool 1024
    const size_t smem1 = (size_t)(546 * 68 + 12288 + 128 + 176 + 1024) * 4;  // 202,976 B
    const size_t smem2 = (size_t)(580 * 68 + 12288 + 128 + 176 + 1024) * 4;  // 212,224 B
    cudaFuncSetAttribute(layer_kernel<1, false>,
                         cudaFuncAttributeMaxDynamicSharedMemorySize, (int)smem1);
    cudaFuncSetAttribute(layer_kernel<2, true>,
                         cudaFuncAttributeMaxDynamicSharedMemorySize, (int)smem2);

    prep_kernel<<<(9 * 64 + 2 * 192 * 64 + 255) / 256, 256>>>(gw0, gw1, gw2, tcw);
    adjprep_kernel<<<1, 32>>>(adj);

    dim3 g0(TDIM / TT, BATCH);     // 128 x 32
    blk0_kernel<<<g0, 512>>>(kpts, bns, bnb, bnm, bnv, bufA);

    dim3 gl(NCTA, BATCH);          // 73 x 32
    layer_kernel<1, false><<<gl, 512, smem1>>>(
        bufA, MT1, bns + 64,  bnb + 64,  bnm + 64,  bnv + 64,  bufB);
    layer_kernel<2, true><<<gl, 512, smem2>>>(
        bufB, MT2, bns + 128, bnb + 128, bnm + 128, bnv + 128, nullptr);

    head_kernel<<<BATCH, 64>>>(lns, lnb, fw, fb, outp);
}

// round 11
// speedup vs baseline: 4.8094x; 1.0477x over previous
#include <cuda_runtime.h>

// ---------------- problem constants ----------------
#define BATCH 32
#define TDIM  2048
#define KP    17
#define HID   64
#define NPOS  (TDIM * KP)   // 34816
#define TT    16            // blk0 time tile
#define CPOS  480           // output positions per layer CTA
#define GR    512           // GEMM rows per CTA (CPOS + 2*16 halo)
#define NCTA  73            // ceil(NPOS / CPOS)
#define NZ    5
#define LTH   1024          // layer kernel threads

typedef unsigned long long ull;
typedef unsigned int u32;

// ---------------- device scratch ----------------
__device__ float g_bufA[(size_t)BATCH * NPOS * HID];
__device__ float g_bufB[(size_t)BATCH * NPOS * HID];
__device__ float g_M0[9 * 64];            // blk0 folded weights (fp32)
__device__ float g_MTf1[24 * 8 * 64];     // layer1 B, fragment-major tf32
__device__ float g_MTf2[24 * 8 * 64];     // layer2 B
__device__ float2 g_adjD[KP * NZ];        // {w, bitcast((k_e - v)*68)} row-delta gathers
__device__ float2 g_adjT0[KP * NZ];       // {w, bitcast(k*3)} for blk0
__device__ float g_part[(size_t)BATCH * 80 * 64];   // pool partials

// ---------------- helpers ----------------
__device__ __forceinline__ ull pack2_dup(float x) {
    ull r; u32 xb = __float_as_uint(x);
    asm("mov.b64 %0, {%1, %1};" : "=l"(r) : "r"(xb));
    return r;
}
__device__ __forceinline__ void fma2(ull& c, ull a, ull b) {
    asm("fma.rn.f32x2 %0, %1, %2, %3;" : "=l"(c) : "l"(a), "l"(b), "l"(c));
}
__device__ __forceinline__ float2 unpack2(ull v) {
    u32 lo, hi;
    asm("mov.b64 {%0, %1}, %2;" : "=r"(lo), "=r"(hi) : "l"(v));
    return make_float2(__uint_as_float(lo), __uint_as_float(hi));
}
__device__ __forceinline__ u32 f2tf(float f) {
    u32 u; asm("cvt.rna.tf32.f32 %0, %1;" : "=r"(u) : "f"(f)); return u;
}
__device__ __forceinline__ void mma_tf32(float* c, const u32* a, const u32* b) {
    asm volatile(
        "mma.sync.aligned.m16n8k8.row.col.f32.tf32.tf32.f32 "
        "{%0,%1,%2,%3}, {%4,%5,%6,%7}, {%8,%9}, {%0,%1,%2,%3};"
        : "+f"(c[0]), "+f"(c[1]), "+f"(c[2]), "+f"(c[3])
        : "r"(a[0]), "r"(a[1]), "r"(a[2]), "r"(a[3]), "r"(b[0]), "r"(b[1]));
}

// ---------------- weight folding (fragment-major for layers 1/2) ----------------
__global__ void prep_kernel(const float* __restrict__ gw0,
                            const float* __restrict__ gw1,
                            const float* __restrict__ gw2,
                            const float* __restrict__ tcw) {
    int id = blockIdx.x * blockDim.x + threadIdx.x;
    const int n0 = 9 * 64, n1 = 192 * 64;
    if (id >= n0 + 2 * n1) return;
    int blk, cin, e; const float* gw;
    if (id < n0)           { blk = 0; cin = 3;  gw = gw0; e = id; }
    else if (id < n0 + n1) { blk = 1; cin = 64; gw = gw1; e = id - n0; }
    else                   { blk = 2; cin = 64; gw = gw2; e = id - n0 - n1; }
    int km = e / 64, o = e % 64;
    int j = km / cin, c = km % cin;
    const float* tw = tcw + (size_t)blk * HID * HID * 3;
    float s = 0.f;
    for (int h = 0; h < HID; ++h)
        s = fmaf(gw[c * HID + h], tw[(o * HID + h) * 3 + j], s);
    if (blk == 0) { g_M0[km * 64 + o] = s; return; }
    // fragment-major slot: thread lane (g,tig) holds B[km=s8*8+tig+4h][o=8i+g]
    int s8 = km >> 3, r8 = km & 7;
    int tig = r8 & 3, h = r8 >> 2;
    int i = o >> 3, g = o & 7;
    int slot = ((s8 * 8 + i) * 32 + (g * 4 + tig)) * 2 + h;
    float* MT = (blk == 1) ? g_MTf1 : g_MTf2;
    MT[slot] = __uint_as_float(f2tf(s));
}

__global__ void adjprep_kernel(const float* __restrict__ adj) {
    int v = threadIdx.x;
    if (v >= KP) return;
    int cnt = 0;
    for (int k = 0; k < KP; ++k) {
        float w = adj[k * KP + v];
        if (w != 0.0f && cnt < NZ) {
            g_adjD [v * NZ + cnt] = make_float2(w, __int_as_float((k - v) * 68));
            g_adjT0[v * NZ + cnt] = make_float2(w, __int_as_float(k * 3));
            ++cnt;
        }
    }
    for (; cnt < NZ; ++cnt) {
        g_adjD [v * NZ + cnt] = make_float2(0.0f, __int_as_float(0));
        g_adjT0[v * NZ + cnt] = make_float2(0.0f, __int_as_float(0));
    }
}

// ---------------- block 0 (fp32 FFMA2 path, CIN=3) ----------------
__global__ void __launch_bounds__(512) blk0_kernel(
    const float* __restrict__ kpts,
    const float* __restrict__ bns, const float* __restrict__ bnb,
    const float* __restrict__ bnm, const float* __restrict__ bnv,
    float* __restrict__ out)
{
    constexpr int PR = (TT + 2) * KP;   // 306
    __shared__ float  sM0[9 * 64];
    __shared__ ull    sZ[PR * 4];
    __shared__ float  sBN[128];
    __shared__ float2 sT[KP * NZ];

    const int tid = threadIdx.x;
    const int b   = blockIdx.y;
    const int t0  = blockIdx.x * TT;

    for (int i = tid; i < 9 * 64; i += 512) sM0[i] = g_M0[i];
    if (tid < KP * NZ) sT[tid] = g_adjT0[tid];
    if (tid < 64) {
        float inv = __ldg(bns + tid) * rsqrtf(__ldg(bnv + tid) + 1e-5f);
        sBN[tid] = inv;
        sBN[64 + tid] = __ldg(bnb + tid) - __ldg(bnm + tid) * inv;
    }
    __syncthreads();

    for (int idx = tid; idx < PR * 3; idx += 512) {
        int ph = idx / 3, c = idx - ph * 3;
        int h = ph / KP, kk = ph - h * KP;
        int t = t0 - 1 + h;
        float v = 0.f;
        if ((unsigned)t < (unsigned)TDIM) {
            const float* xr = kpts + (size_t)(b * TDIM + t) * (KP * 3);
#pragma unroll
            for (int e = 0; e < NZ; ++e) {
                float2 wt = sT[kk * NZ + e];
                v = fmaf(wt.x, xr[__float_as_int(wt.y) + c], v);
            }
        }
        sZ[ph * 4 + c] = pack2_dup(v);
    }
    __syncthreads();

    const int cg = tid & 7, rt = tid >> 3;
    const int o1 = cg * 4, o2 = 32 + o1;
    const size_t gb = (size_t)(b * TDIM + t0) * KP;
    const float4 invA = *(const float4*)(sBN + o1);
    const float4 invB = *(const float4*)(sBN + o2);
    const float4 betA = *(const float4*)(sBN + 64 + o1);
    const float4 betB = *(const float4*)(sBN + 64 + o2);

    for (int it = 0; it < 2; ++it) {
        bool act = (it == 0) || (tid < 32);
        if (!act) continue;
        const int prow = (it ? 64 + rt : rt);

        ull acc[4][4] = {};
#pragma unroll
        for (int j = 0; j < 3; ++j) {
            const ull* zb = sZ + (prow + j * KP) * 4;
#pragma unroll
            for (int c = 0; c < 3; ++c) {
                const float* mk = sM0 + (j * 3 + c) * 64;
                ulonglong2 m1 = *(const ulonglong2*)(mk + o1);
                ulonglong2 m2 = *(const ulonglong2*)(mk + o2);
#pragma unroll
                for (int i = 0; i < 4; ++i) {
                    ull av = zb[i * 68 * 4 + c];
                    fma2(acc[i][0], av, m1.x); fma2(acc[i][1], av, m1.y);
                    fma2(acc[i][2], av, m2.x); fma2(acc[i][3], av, m2.y);
                }
            }
        }
#pragma unroll
        for (int i = 0; i < 4; ++i) {
            float2 q0 = unpack2(acc[i][0]), q1 = unpack2(acc[i][1]);
            float2 q2 = unpack2(acc[i][2]), q3 = unpack2(acc[i][3]);
            size_t rowo = (gb + prow + 68 * i) * 64;
            float4 v1, v2;
            v1.x = fmaxf(fmaf(q0.x, invA.x, betA.x), 0.f);
            v1.y = fmaxf(fmaf(q0.y, invA.y, betA.y), 0.f);
            v1.z = fmaxf(fmaf(q1.x, invA.z, betA.z), 0.f);
            v1.w = fmaxf(fmaf(q1.y, invA.w, betA.w), 0.f);
            v2.x = fmaxf(fmaf(q2.x, invB.x, betB.x), 0.f);
            v2.y = fmaxf(fmaf(q2.y, invB.y, betB.y), 0.f);
            v2.z = fmaxf(fmaf(q3.x, invB.z, betB.z), 0.f);
            v2.w = fmaxf(fmaf(q3.y, invB.w, betB.w), 0.f);
            *(float4*)(out + rowo + o1) = v1;
            *(float4*)(out + rowo + o2) = v2;
        }
    }
}

// ---------------- layers 1 & 2: raw-GEMM + epilogue adj-mix (1024 thr) ----------------
template <int DIL, bool POOL>
__global__ void __launch_bounds__(LTH) layer_kernel(
    const float* __restrict__ Y,
    const float* __restrict__ MTf,
    const float* __restrict__ bns, const float* __restrict__ bnb,
    const float* __restrict__ bnm, const float* __restrict__ bnv,
    float* __restrict__ outp)
{
    constexpr int NSH = KP * DIL;
    constexpr int RA  = GR + 2 * NSH;       // 546 / 580
    constexpr int ZS  = 68;
    constexpr int OFF_B   = RA * ZS;
    constexpr int OFF_INV = OFF_B + 12288;
    constexpr int OFF_BET = OFF_INV + 64;
    constexpr int OFF_T   = OFF_BET + 64;
    constexpr int OFF_PL  = OFF_T + 176;     // 16B-aligned

    extern __shared__ float sm[];
    u32*    sZu  = (u32*)sm;                 // raw A slab (k-permuted tf32)
    u32*    sBf  = (u32*)(sm + OFF_B);       // B fragment-major
    float*  sInv = sm + OFF_INV;
    float*  sBet = sm + OFF_BET;
    float2* sT   = (float2*)(sm + OFF_T);
    float*  sPl  = sm + OFF_PL;              // 32*64 floats
    float*  sD   = sm;                       // D buffer aliases slab (post-GEMM)

    const int tid = threadIdx.x;
    const int wid = tid >> 5, lid = tid & 31;
    const int g = lid >> 2, tig = lid & 3;
    const int b = blockIdx.y;
    const int p0 = blockIdx.x * CPOS;
    const int pbase = p0 - 16 - NSH;         // position of slab row 0
    const float* Yb = Y + (size_t)b * NPOS * 64;

    if (tid < KP * NZ) sT[tid] = g_adjD[tid];
    if (tid < 64) {
        float inv = __ldg(bns + tid) * rsqrtf(__ldg(bnv + tid) + 1e-5f);
        sInv[tid] = inv;
        sBet[tid] = __ldg(bnb + tid) - __ldg(bnm + tid) * inv;
    }
    // B: linear copy (prep wrote fragment-major)
    for (int i = tid; i < 3072; i += LTH)
        *(uint4*)(sBf + i * 4) = *(const uint4*)(MTf + i * 4);

    // raw A staging: 1x coalesced, channel-permuted within 8-groups, tf32
    for (int idx = tid; idx < RA * 8; idx += LTH) {
        int zr = idx >> 3, g8 = idx & 7;
        int p = pbase + zr;
        uint4 d0 = make_uint4(0, 0, 0, 0), d1 = make_uint4(0, 0, 0, 0);
        if ((unsigned)p < (unsigned)NPOS) {
            const float4 q0 = *(const float4*)(Yb + (size_t)p * 64 + g8 * 8);
            const float4 q1 = *(const float4*)(Yb + (size_t)p * 64 + g8 * 8 + 4);
            d0.x = f2tf(q0.x); d0.y = f2tf(q1.x); d0.z = f2tf(q0.y); d0.w = f2tf(q1.y);
            d1.x = f2tf(q0.z); d1.y = f2tf(q1.z); d1.z = f2tf(q0.w); d1.w = f2tf(q1.w);
        }
        u32* zp = sZu + zr * ZS + g8 * 8;
        *(uint4*)zp       = d0;
        *(uint4*)(zp + 4) = d1;
    }
    __syncthreads();

    // ---- GEMM: warp owns GEMM rows [wid*16, wid*16+16) = 1 m16 tile ----
    float c[8][4];
#pragma unroll
    for (int i = 0; i < 8; ++i)
#pragma unroll
        for (int n = 0; n < 4; ++n) c[i][n] = 0.f;

#pragma unroll
    for (int tap = 0; tap < 3; ++tap) {
        const u32* za = sZu + (wid * 16 + tap * NSH + g) * ZS + 2 * tig;
#pragma unroll
        for (int k8 = 0; k8 < 8; ++k8) {
            const u32* zp = za + k8 * 8;
            u32 a[4];
            { uint2 v = *(const uint2*)zp;             a[0] = v.x; a[2] = v.y; }
            { uint2 v = *(const uint2*)(zp + 8 * ZS);  a[1] = v.x; a[3] = v.y; }
            const u32* bb = sBf + ((tap * 8 + k8) * 8) * 64 + lid * 2;
#pragma unroll
            for (int i = 0; i < 8; ++i) {
                uint2 bv = *(const uint2*)(bb + i * 64);
                u32 bf[2] = {bv.x, bv.y};
                mma_tf32(c[i], a, bf);
            }
        }
    }
    __syncthreads();   // all slab reads done; reuse as D buffer

    // ---- D store: rows stride 68, logical channels ----
    {
        const int r0 = wid * 16 + g;
#pragma unroll
        for (int i = 0; i < 8; ++i) {
            *(float2*)(sD + r0 * ZS + 8 * i + 2 * tig)       = make_float2(c[i][0], c[i][1]);
            *(float2*)(sD + (r0 + 8) * ZS + 8 * i + 2 * tig) = make_float2(c[i][2], c[i][3]);
        }
    }
    __syncthreads();

    // ---- epilogue: adj-mix from D + BN + ReLU + residual (+ pool) ----
    const int c4 = tid & 15;                 // channel quad, constant per thread
    const float4 inv4 = *(const float4*)(sInv + c4 * 4);
    const float4 bet4 = *(const float4*)(sBet + c4 * 4);
    float ps[4] = {0.f, 0.f, 0.f, 0.f};
    float* ob = outp ? (outp + (size_t)b * NPOS * 64) : nullptr;

    int r = tid >> 4;                        // output row, advances by 64
    int p = p0 + r;
    int k = p % KP;                          // one div total; then k += 13 mod 17
    const float* drow = sD + (r + 16) * ZS + c4 * 4;
    const float* rres = Yb + (size_t)p * 64 + c4 * 4;
    float* wout = ob ? (ob + (size_t)p * 64 + c4 * 4) : nullptr;

#pragma unroll 2
    for (int it = 0; it < 8; ++it) {
        if (r < CPOS && p < NPOS) {
            const float2* tk = sT + k * NZ;
            float4 s = make_float4(0.f, 0.f, 0.f, 0.f);
#pragma unroll
            for (int e = 0; e < NZ; ++e) {
                float2 wt = tk[e];
                const float4 dv = *(const float4*)(drow + __float_as_int(wt.y));
                s.x = fmaf(wt.x, dv.x, s.x);
                s.y = fmaf(wt.x, dv.y, s.y);
                s.z = fmaf(wt.x, dv.z, s.z);
                s.w = fmaf(wt.x, dv.w, s.w);
            }
            const float4 rs = *(const float4*)rres;
            float4 v;
            v.x = fmaxf(fmaf(s.x, inv4.x, bet4.x), 0.f) + rs.x;
            v.y = fmaxf(fmaf(s.y, inv4.y, bet4.y), 0.f) + rs.y;
            v.z = fmaxf(fmaf(s.z, inv4.z, bet4.z), 0.f) + rs.z;
            v.w = fmaxf(fmaf(s.w, inv4.w, bet4.w), 0.f) + rs.w;
            if (POOL) {
                ps[0] += v.x; ps[1] += v.y; ps[2] += v.z; ps[3] += v.w;
            } else {
                *(float4*)wout = v;
            }
        }
        r += 64; p += 64;
        k += 13; if (k >= KP) k -= KP;
        drow += 64 * ZS;
        rres += 64 * 64;
        if (!POOL) wout += 64 * 64;
    }

    if (POOL) {
        // lanes l and l+16 share c4 within a warp
#pragma unroll
        for (int j = 0; j < 4; ++j)
            ps[j] += __shfl_xor_sync(0xFFFFFFFF, ps[j], 16);
        if (lid < 16) {
            *(float4*)(sPl + wid * 64 + lid * 4) = make_float4(ps[0], ps[1], ps[2], ps[3]);
        }
        __syncthreads();
        if (tid < 64) {
            float s = 0.f;
            for (int w = 0; w < 32; ++w)
                s += sPl[w * 64 + tid];
            g_part[((size_t)b * 80 + blockIdx.x) * 64 + tid] = s;
        }
    }
}

// ---------------- head: pool finish + LN + FC ----------------
__global__ void head_kernel(const float* __restrict__ lns, const float* __restrict__ lnb,
                            const float* __restrict__ fw,  const float* __restrict__ fb,
                            float* __restrict__ outp) {
    __shared__ float f[64];
    __shared__ float mu_s, rv_s;
    const int b = blockIdx.x, tid = threadIdx.x;
    float s = 0.f;
    for (int i = 0; i < NCTA; ++i)
        s += g_part[((size_t)b * 80 + i) * 64 + tid];
    float v = s * (1.0f / (float)NPOS);
    f[tid] = v;
    __syncthreads();
    if (tid == 0) {
        float m = 0.f;
        for (int i = 0; i < 64; ++i) m += f[i];
        m *= (1.0f / 64.0f);
        float va = 0.f;
        for (int i = 0; i < 64; ++i) { float d = f[i] - m; va = fmaf(d, d, va); }
        va *= (1.0f / 64.0f);
        mu_s = m; rv_s = rsqrtf(va + 1e-5f);
    }
    __syncthreads();
    float nf = (v - mu_s) * rv_s * lns[tid] + lnb[tid];
    __syncthreads();
    f[tid] = nf;
    __syncthreads();
    if (tid < 10) {
        float o = fb[tid];
        for (int c = 0; c < 64; ++c)
            o = fmaf(f[c], fw[c * 10 + tid], o);
        outp[b * 10 + tid] = o;
    }
}

// ---------------- launch ----------------
extern "C" void kernel_launch(void* const* d_in, const int* in_sizes, int n_in,
                              void* d_out, int out_size) {
    const float* kpts = (const float*)d_in[0];
    const float* adj  = (const float*)d_in[1];
    const float* gw0  = (const float*)d_in[2];
    const float* gw1  = (const float*)d_in[3];
    const float* gw2  = (const float*)d_in[4];
    const float* tcw  = (const float*)d_in[5];
    const float* bns  = (const float*)d_in[6];
    const float* bnb  = (const float*)d_in[7];
    const float* bnm  = (const float*)d_in[8];
    const float* bnv  = (const float*)d_in[9];
    const float* lns  = (const float*)d_in[10];
    const float* lnb  = (const float*)d_in[11];
    const float* fw   = (const float*)d_in[12];
    const float* fb   = (const float*)d_in[13];
    float* outp = (float*)d_out;

    float *bufA, *bufB, *MT1, *MT2;
    cudaGetSymbolAddress((void**)&bufA, g_bufA);
    cudaGetSymbolAddress((void**)&bufB, g_bufB);
    cudaGetSymbolAddress((void**)&MT1, g_MTf1);
    cudaGetSymbolAddress((void**)&MT2, g_MTf2);

    // smem floats: slab RA*68 + B 12288 + inv/bet 128 + adjD pad 176 + pool 2048
    const size_t smem1 = (size_t)(546 * 68 + 12288 + 128 + 176 + 2048) * 4;  // 207,072 B
    const size_t smem2 = (size_t)(580 * 68 + 12288 + 128 + 176 + 2048) * 4;  // 216,320 B
    cudaFuncSetAttribute(layer_kernel<1, false>,
                         cudaFuncAttributeMaxDynamicSharedMemorySize, (int)smem1);
    cudaFuncSetAttribute(layer_kernel<2, true>,
                         cudaFuncAttributeMaxDynamicSharedMemorySize, (int)smem2);

    prep_kernel<<<(9 * 64 + 2 * 192 * 64 + 255) / 256, 256>>>(gw0, gw1, gw2, tcw);
    adjprep_kernel<<<1, 32>>>(adj);

    dim3 g0(TDIM / TT, BATCH);     // 128 x 32
    blk0_kernel<<<g0, 512>>>(kpts, bns, bnb, bnm, bnv, bufA);

    dim3 gl(NCTA, BATCH);          // 73 x 32
    layer_kernel<1, false><<<gl, LTH, smem1>>>(
        bufA, MT1, bns + 64,  bnb + 64,  bnm + 64,  bnv + 64,  bufB);
    layer_kernel<2, true><<<gl, LTH, smem2>>>(
        bufB, MT2, bns + 128, bnb + 128, bnm + 128, bnv + 128, nullptr);

    head_kernel<<<BATCH, 64>>>(lns, lnb, fw, fb, outp);
}